// round 1
// baseline (speedup 1.0000x reference)
#include <cuda_runtime.h>
#include <math.h>

#define B_ 2
#define S_ 2048
#define C_ 1536
#define HQ_ 16
#define HKV_ 4
#define DQK_ 128
#define DV_ 96
#define EPSF 1e-5f

// ---------------- scratch (static __device__, no allocation) ----------------
__device__ float g_h[B_*S_*C_];          // 25.2 MB
__device__ float g_q[B_*S_*HQ_*DQK_];    // 33.6 MB
__device__ float g_k[B_*S_*HKV_*DQK_];   //  8.4 MB
__device__ float g_v[B_*S_*HKV_*DV_];    //  6.3 MB
__device__ float g_y[B_*S_*HQ_*DV_];     // 25.2 MB

// ---------------- 1. rms_bn1: h = x * g * rsqrt(ms+eps) ----------------
__global__ void rmsbn1_kernel(const float* __restrict__ x, const float* __restrict__ g,
                              const float* __restrict__ ms) {
    int i = blockIdx.x * blockDim.x + threadIdx.x;
    int idx = i * 4;
    if (idx >= B_*S_*C_) return;
    float4 xv = *(const float4*)(x + idx);
    int c = idx % C_;                       // C_ % 4 == 0 so c..c+3 within a row
    float4 o;
    o.x = xv.x * g[c+0] * rsqrtf(ms[c+0] + EPSF);
    o.y = xv.y * g[c+1] * rsqrtf(ms[c+1] + EPSF);
    o.z = xv.z * g[c+2] * rsqrtf(ms[c+2] + EPSF);
    o.w = xv.w * g[c+3] * rsqrtf(ms[c+3] + EPSF);
    *(float4*)(g_h + idx) = o;
}

// ---------------- 2. generic SGEMM 128x128x8, 8x8 microtile ----------------
// C[m,n] = sum_k A[m,k]*B[k,n]; EPI: C = (acc + bias[n]) * (bng[n]*rsqrt(bnms[n]+eps))
template<bool EPI>
__global__ void __launch_bounds__(256) sgemm_kernel(
    const float* __restrict__ A, const float* __restrict__ Bm, float* __restrict__ Cm,
    int M, int N, int K,
    const float* __restrict__ bias, const float* __restrict__ bng,
    const float* __restrict__ bnms)
{
    __shared__ float As[8][128];
    __shared__ float Bs[8][128];
    int tid = threadIdx.x;
    int tx = tid & 15, ty = tid >> 4;
    const float* Ab = A + (size_t)blockIdx.y * 128 * K;
    const float* Bb = Bm + blockIdx.x * 128;
    float acc[8][8] = {};
    int arow = tid >> 1, acol = (tid & 1) * 4;
    int brow = tid >> 5, bcol = (tid & 31) * 4;

    for (int k0 = 0; k0 < K; k0 += 8) {
        float4 a = *(const float4*)(Ab + (size_t)arow * K + k0 + acol);
        As[acol+0][arow] = a.x; As[acol+1][arow] = a.y;
        As[acol+2][arow] = a.z; As[acol+3][arow] = a.w;
        *(float4*)&Bs[brow][bcol] = *(const float4*)(Bb + (size_t)(k0 + brow) * N + bcol);
        __syncthreads();
        #pragma unroll
        for (int kk = 0; kk < 8; kk++) {
            float ra[8], rb[8];
            #pragma unroll
            for (int i = 0; i < 8; i++) ra[i] = As[kk][ty*8 + i];
            #pragma unroll
            for (int j = 0; j < 8; j++) rb[j] = Bs[kk][tx*8 + j];
            #pragma unroll
            for (int i = 0; i < 8; i++)
                #pragma unroll
                for (int j = 0; j < 8; j++)
                    acc[i][j] = fmaf(ra[i], rb[j], acc[i][j]);
        }
        __syncthreads();
    }

    int row0 = blockIdx.y * 128 + ty * 8;
    int col0 = blockIdx.x * 128 + tx * 8;
    #pragma unroll
    for (int i = 0; i < 8; i++) {
        #pragma unroll
        for (int j0 = 0; j0 < 8; j0 += 4) {
            float4 o;
            float* po = &o.x;
            #pragma unroll
            for (int u = 0; u < 4; u++) {
                float vv = acc[i][j0+u];
                if (EPI) {
                    int col = col0 + j0 + u;
                    vv = (vv + bias[col]) * (bng[col] * rsqrtf(bnms[col] + EPSF));
                }
                po[u] = vv;
            }
            *(float4*)(Cm + (size_t)(row0 + i) * N + col0 + j0) = o;
        }
    }
}

// ---------------- 3. per-head LayerNorm (+ optional RoPE), one warp per vector ----
template<int D, bool ROPE, int H>
__global__ void ln_head_kernel(float* __restrict__ data, const float* __restrict__ gg,
                               const float* __restrict__ bb) {
    const int NV = D / 32;
    int gw = (blockIdx.x * blockDim.x + threadIdx.x) >> 5;
    int lane = threadIdx.x & 31;
    float* row = data + (size_t)gw * D;
    int s = (gw / H) % S_;                 // position within sequence
    int d0 = lane * NV;

    float vals[NV];
    #pragma unroll
    for (int i = 0; i < NV; i++) vals[i] = row[d0 + i];

    float sum = 0.f, sq = 0.f;
    #pragma unroll
    for (int i = 0; i < NV; i++) { sum += vals[i]; sq += vals[i]*vals[i]; }
    #pragma unroll
    for (int off = 16; off > 0; off >>= 1) {
        sum += __shfl_xor_sync(0xffffffffu, sum, off);
        sq  += __shfl_xor_sync(0xffffffffu, sq,  off);
    }
    float mean = sum * (1.0f / D);
    float var  = sq  * (1.0f / D) - mean * mean;
    float inv  = rsqrtf(var + EPSF);
    #pragma unroll
    for (int i = 0; i < NV; i++)
        vals[i] = (vals[i] - mean) * inv * gg[d0 + i] + bb[d0 + i];

    if (ROPE) {
        // inv_freq_i = 1/(i + 1985^(i/63)); double for accuracy vs f32 reference
        const double lg63 = log(1985.0) / 63.0;
        #pragma unroll
        for (int p = 0; p < NV/2; p++) {
            int fi = (d0 >> 1) + p;
            double geom = exp((double)fi * lg63);
            float invf = (float)(1.0 / ((double)fi + geom));
            float theta = (float)s * invf;
            float sn, cs;
            sincosf(theta, &sn, &cs);
            float x0 = vals[2*p], x1 = vals[2*p + 1];
            vals[2*p]     = x0 * cs - x1 * sn;
            vals[2*p + 1] = x1 * cs + x0 * sn;
        }
    }
    #pragma unroll
    for (int i = 0; i < NV; i++) row[d0 + i] = vals[i];
}

// ---------------- 4. flash attention (tanh-capped => no running max needed) ------
// grid: (B*HQ, S/64); 256 threads; 64 query rows x 64-key tiles, full fp32
#define QK_STRIDE 132
#define VT_STRIDE 68

__global__ void __launch_bounds__(256) flash_kernel() {
    extern __shared__ float sm[];
    float* Qs  = sm;                          // [64][132]
    float* Ks  = Qs + 64 * QK_STRIDE;         // [64][132]
    float* Vt  = Ks + 64 * QK_STRIDE;         // [96][68]  (transposed: [dv][key])
    float* Ps  = Vt + 96 * VT_STRIDE;         // [64][64]
    float* Red = Ps + 64 * 64;                // [64][16]

    int bh = blockIdx.x;
    int b = bh / HQ_, h = bh % HQ_;
    int kv = h % HKV_;                        // tile-repeat: q head h uses kv head h%4
    int s0 = blockIdx.y * 64;
    int tid = threadIdx.x;
    int tr = tid >> 4, tc = tid & 15;

    // load Q tile [64][128]
    for (int t = tid; t < 64 * 32; t += 256) {
        int r = t >> 5, c4 = (t & 31) * 4;
        float4 qv = *(const float4*)(g_q + ((size_t)((b*S_ + s0 + r)*HQ_ + h))*DQK_ + c4);
        *(float4*)(Qs + r * QK_STRIDE + c4) = qv;
    }

    float acc[4][6];
    float rs[4];
    #pragma unroll
    for (int i = 0; i < 4; i++) {
        rs[i] = 0.f;
        #pragma unroll
        for (int j = 0; j < 6; j++) acc[i][j] = 0.f;
    }

    const float scl = 0.08838834764831845f;   // 1/sqrt(128)

    for (int t0 = 0; t0 < S_; t0 += 64) {
        __syncthreads();   // protect K/V smem from previous iteration's readers
        // load K tile [64][128]
        for (int t = tid; t < 64 * 32; t += 256) {
            int r = t >> 5, c4 = (t & 31) * 4;
            float4 kvv = *(const float4*)(g_k + ((size_t)((b*S_ + t0 + r)*HKV_ + kv))*DQK_ + c4);
            *(float4*)(Ks + r * QK_STRIDE + c4) = kvv;
        }
        // load V tile [64][96] -> transposed Vt[dv][key]
        for (int t = tid; t < 64 * 24; t += 256) {
            int r = t / 24, c4 = (t % 24) * 4;
            float4 vv = *(const float4*)(g_v + ((size_t)((b*S_ + t0 + r)*HKV_ + kv))*DV_ + c4);
            Vt[(c4+0)*VT_STRIDE + r] = vv.x;
            Vt[(c4+1)*VT_STRIDE + r] = vv.y;
            Vt[(c4+2)*VT_STRIDE + r] = vv.z;
            Vt[(c4+3)*VT_STRIDE + r] = vv.w;
        }
        __syncthreads();

        // S = Q K^T : thread owns rows {4tr+i}, cols {tc+16j}
        float sacc[4][4];
        #pragma unroll
        for (int i = 0; i < 4; i++)
            #pragma unroll
            for (int j = 0; j < 4; j++) sacc[i][j] = 0.f;

        #pragma unroll 2
        for (int k0 = 0; k0 < DQK_; k0 += 4) {
            float4 qreg[4], kreg[4];
            #pragma unroll
            for (int i = 0; i < 4; i++) qreg[i] = *(float4*)(Qs + (4*tr + i)*QK_STRIDE + k0);
            #pragma unroll
            for (int j = 0; j < 4; j++) kreg[j] = *(float4*)(Ks + (tc + 16*j)*QK_STRIDE + k0);
            #pragma unroll
            for (int i = 0; i < 4; i++)
                #pragma unroll
                for (int j = 0; j < 4; j++) {
                    sacc[i][j] = fmaf(qreg[i].x, kreg[j].x, sacc[i][j]);
                    sacc[i][j] = fmaf(qreg[i].y, kreg[j].y, sacc[i][j]);
                    sacc[i][j] = fmaf(qreg[i].z, kreg[j].z, sacc[i][j]);
                    sacc[i][j] = fmaf(qreg[i].w, kreg[j].w, sacc[i][j]);
                }
        }

        // P = exp(5*tanh(s/5)); logits bounded in [-5,5] so no max tracking
        #pragma unroll
        for (int i = 0; i < 4; i++)
            #pragma unroll
            for (int j = 0; j < 4; j++) {
                float sv = sacc[i][j] * scl;
                float p = expf(5.0f * tanhf(sv * 0.2f));
                rs[i] += p;
                Ps[(4*tr + i)*64 + tc + 16*j] = p;
            }
        __syncthreads();

        // acc += P @ V  (dot over keys; both P and Vt are key-contiguous)
        #pragma unroll 2
        for (int k0 = 0; k0 < 64; k0 += 4) {
            float4 pr[4], vr[6];
            #pragma unroll
            for (int i = 0; i < 4; i++) pr[i] = *(float4*)(Ps + (4*tr + i)*64 + k0);
            #pragma unroll
            for (int j = 0; j < 6; j++) vr[j] = *(float4*)(Vt + (tc + 16*j)*VT_STRIDE + k0);
            #pragma unroll
            for (int i = 0; i < 4; i++)
                #pragma unroll
                for (int j = 0; j < 6; j++) {
                    acc[i][j] = fmaf(pr[i].x, vr[j].x, acc[i][j]);
                    acc[i][j] = fmaf(pr[i].y, vr[j].y, acc[i][j]);
                    acc[i][j] = fmaf(pr[i].z, vr[j].z, acc[i][j]);
                    acc[i][j] = fmaf(pr[i].w, vr[j].w, acc[i][j]);
                }
        }
    }
    __syncthreads();

    // reduce row sums across the 16 tc-threads, normalize, write y[b,s,h,dv]
    #pragma unroll
    for (int i = 0; i < 4; i++) Red[(4*tr + i)*16 + tc] = rs[i];
    __syncthreads();
    #pragma unroll
    for (int i = 0; i < 4; i++) {
        float tot = 0.f;
        #pragma unroll
        for (int t = 0; t < 16; t++) tot += Red[(4*tr + i)*16 + t];
        float invt = 1.0f / tot;
        size_t base = ((size_t)((b*S_ + s0 + 4*tr + i)*HQ_ + h)) * DV_;
        #pragma unroll
        for (int j = 0; j < 6; j++)
            g_y[base + tc + 16*j] = acc[i][j] * invt;
    }
}

// ---------------- launch ----------------
extern "C" void kernel_launch(void* const* d_in, const int* in_sizes, int n_in,
                              void* d_out, int out_size) {
    const float* x      = (const float*)d_in[0];
    const float* bn1_g  = (const float*)d_in[1];
    const float* bn1_ms = (const float*)d_in[2];
    const float* Wq     = (const float*)d_in[3];
    const float* Wk     = (const float*)d_in[4];
    const float* Wv     = (const float*)d_in[5];
    const float* qn_g   = (const float*)d_in[6];
    const float* qn_b   = (const float*)d_in[7];
    const float* kn_g   = (const float*)d_in[8];
    const float* kn_b   = (const float*)d_in[9];
    const float* vn_g   = (const float*)d_in[10];
    const float* vn_b   = (const float*)d_in[11];
    const float* Wo     = (const float*)d_in[12];
    const float* bo     = (const float*)d_in[13];
    const float* bn2_g  = (const float*)d_in[14];
    const float* bn2_ms = (const float*)d_in[15];
    float* out = (float*)d_out;

    float *ph, *pq, *pk, *pv, *py;
    cudaGetSymbolAddress((void**)&ph, g_h);
    cudaGetSymbolAddress((void**)&pq, g_q);
    cudaGetSymbolAddress((void**)&pk, g_k);
    cudaGetSymbolAddress((void**)&pv, g_v);
    cudaGetSymbolAddress((void**)&py, g_y);

    const int M = B_ * S_;   // 4096

    // 1. rms_bn1
    rmsbn1_kernel<<<(B_*S_*C_/4 + 255)/256, 256>>>(x, bn1_g, bn1_ms);

    // 2. QKV projections
    sgemm_kernel<false><<<dim3((HQ_*DQK_)/128,  M/128), 256>>>(ph, Wq, pq, M, HQ_*DQK_,  C_, nullptr, nullptr, nullptr);
    sgemm_kernel<false><<<dim3((HKV_*DQK_)/128, M/128), 256>>>(ph, Wk, pk, M, HKV_*DQK_, C_, nullptr, nullptr, nullptr);
    sgemm_kernel<false><<<dim3((HKV_*DV_)/128,  M/128), 256>>>(ph, Wv, pv, M, HKV_*DV_,  C_, nullptr, nullptr, nullptr);

    // 3. per-head LN (+RoPE for q,k). One warp per head-vector, 8 warps/block.
    {
        int rows_q = B_*S_*HQ_;   // 65536
        int rows_k = B_*S_*HKV_;  // 16384
        ln_head_kernel<DQK_, true,  HQ_ ><<<rows_q/8, 256>>>(pq, qn_g, qn_b);
        ln_head_kernel<DQK_, true,  HKV_><<<rows_k/8, 256>>>(pk, kn_g, kn_b);
        ln_head_kernel<DV_,  false, HKV_><<<rows_k/8, 256>>>(pv, vn_g, vn_b);
    }

    // 4. attention
    {
        const int smem = (64*QK_STRIDE*2 + 96*VT_STRIDE + 64*64 + 64*16) * 4; // 114176 B
        cudaFuncSetAttribute(flash_kernel, cudaFuncAttributeMaxDynamicSharedMemorySize, smem);
        flash_kernel<<<dim3(B_*HQ_, S_/64), 256, smem>>>();
    }

    // 5. output projection + bias + rms_bn2 (fused epilogue)
    sgemm_kernel<true><<<dim3(C_/128, M/128), 256>>>(py, Wo, out, M, C_, HQ_*DV_, bo, bn2_g, bn2_ms);
}

// round 2
// speedup vs baseline: 2.4886x; 2.4886x over previous
#include <cuda_runtime.h>
#include <math.h>

#define B_ 2
#define S_ 2048
#define C_ 1536
#define HQ_ 16
#define HKV_ 4
#define DQK_ 128
#define DV_ 96
#define EPSF 1e-5f

// ---------------- scratch ----------------
__device__ float g_h[B_*S_*C_];
__device__ float g_q[B_*S_*HQ_*DQK_];
__device__ float g_k[B_*S_*HKV_*DQK_];
__device__ float g_v[B_*S_*HKV_*DV_];
__device__ float g_y[B_*S_*HQ_*DV_];

// ---------------- helpers ----------------
__device__ __forceinline__ unsigned f2tf(float f) {
    unsigned u;
    asm("cvt.rna.tf32.f32 %0, %1;" : "=r"(u) : "f"(f));
    return u;
}
__device__ __forceinline__ void mma_tf32(float c[4], const unsigned a[4], const unsigned b[2]) {
    asm volatile(
        "mma.sync.aligned.m16n8k8.row.col.f32.tf32.tf32.f32 "
        "{%0,%1,%2,%3},{%4,%5,%6,%7},{%8,%9},{%0,%1,%2,%3};"
        : "+f"(c[0]), "+f"(c[1]), "+f"(c[2]), "+f"(c[3])
        : "r"(a[0]), "r"(a[1]), "r"(a[2]), "r"(a[3]), "r"(b[0]), "r"(b[1]));
}
__device__ __forceinline__ void cp16(void* smem, const void* gp) {
    unsigned s = (unsigned)__cvta_generic_to_shared(smem);
    asm volatile("cp.async.cg.shared.global [%0], [%1], 16;\n" :: "r"(s), "l"(gp));
}
__device__ __forceinline__ void cp_commit() { asm volatile("cp.async.commit_group;\n"); }
__device__ __forceinline__ void cp_wait0() { asm volatile("cp.async.wait_group 0;\n"); }

// ---------------- 1. rms_bn1 ----------------
__global__ void rmsbn1_kernel(const float* __restrict__ x, const float* __restrict__ g,
                              const float* __restrict__ ms) {
    int idx = (blockIdx.x * blockDim.x + threadIdx.x) * 4;
    if (idx >= B_*S_*C_) return;
    float4 xv = *(const float4*)(x + idx);
    int c = idx % C_;
    float4 o;
    o.x = xv.x * g[c+0] * rsqrtf(ms[c+0] + EPSF);
    o.y = xv.y * g[c+1] * rsqrtf(ms[c+1] + EPSF);
    o.z = xv.z * g[c+2] * rsqrtf(ms[c+2] + EPSF);
    o.w = xv.w * g[c+3] * rsqrtf(ms[c+3] + EPSF);
    *(float4*)(g_h + idx) = o;
}

// ---------------- 2. tf32 tensor-core GEMM 128x128x32 ----------------
// smem strides (floats): A 36 (conflict-free frag loads), B 136
#define AS_STR 36
#define BS_STR 136
#define AS_BUF (128*AS_STR)   // 4608
#define BS_BUF (32*BS_STR)    // 4352

template<bool EPI>
__global__ void __launch_bounds__(256) tf32gemm_kernel(
    const float* __restrict__ A, const float* __restrict__ Bm, float* __restrict__ Cm,
    int M, int N, int K,
    const float* __restrict__ bias, const float* __restrict__ bng,
    const float* __restrict__ bnms)
{
    extern __shared__ float sm[];
    float* As = sm;                 // [2][128][36]
    float* Bs = sm + 2*AS_BUF;      // [2][32][136]

    int tid = threadIdx.x;
    int lane = tid & 31, wid = tid >> 5;
    int wm = wid & 3, wn = wid >> 2;        // 4 x 2 warps -> 32x64 each
    int g = lane >> 2, q = lane & 3;
    int bx = blockIdx.x, by = blockIdx.y;

    float acc[2][8][4];
    #pragma unroll
    for (int mt = 0; mt < 2; mt++)
        #pragma unroll
        for (int nt = 0; nt < 8; nt++)
            #pragma unroll
            for (int i = 0; i < 4; i++) acc[mt][nt][i] = 0.f;

    const int nk = K / 32;
    // prefetch tile 0
    {
        float* Ad = As; float* Bd = Bs;
        #pragma unroll
        for (int i = 0; i < 4; i++) {
            int f4 = tid + i*256;
            int r = f4 >> 3, c = (f4 & 7) * 4;
            cp16(Ad + r*AS_STR + c, A + (size_t)(by*128 + r)*K + c);
        }
        #pragma unroll
        for (int i = 0; i < 4; i++) {
            int f4 = tid + i*256;
            int r = f4 >> 5, c = (f4 & 31) * 4;
            cp16(Bd + r*BS_STR + c, Bm + (size_t)r*N + bx*128 + c);
        }
        cp_commit();
    }

    for (int kt = 0; kt < nk; kt++) {
        cp_wait0();
        __syncthreads();
        if (kt + 1 < nk) {
            float* Ad = As + ((kt+1)&1)*AS_BUF;
            float* Bd = Bs + ((kt+1)&1)*BS_BUF;
            int k0 = (kt+1)*32;
            #pragma unroll
            for (int i = 0; i < 4; i++) {
                int f4 = tid + i*256;
                int r = f4 >> 3, c = (f4 & 7) * 4;
                cp16(Ad + r*AS_STR + c, A + (size_t)(by*128 + r)*K + k0 + c);
            }
            #pragma unroll
            for (int i = 0; i < 4; i++) {
                int f4 = tid + i*256;
                int r = f4 >> 5, c = (f4 & 31) * 4;
                cp16(Bd + r*BS_STR + c, Bm + (size_t)(k0 + r)*N + bx*128 + c);
            }
            cp_commit();
        }
        const float* Ab = As + (kt&1)*AS_BUF;
        const float* Bb = Bs + (kt&1)*BS_BUF;
        #pragma unroll
        for (int kk = 0; kk < 32; kk += 8) {
            unsigned a[2][4], b[8][2];
            #pragma unroll
            for (int mt = 0; mt < 2; mt++) {
                int r = wm*32 + mt*16 + g;
                a[mt][0] = f2tf(Ab[r*AS_STR + kk + q]);
                a[mt][1] = f2tf(Ab[(r+8)*AS_STR + kk + q]);
                a[mt][2] = f2tf(Ab[r*AS_STR + kk + q + 4]);
                a[mt][3] = f2tf(Ab[(r+8)*AS_STR + kk + q + 4]);
            }
            #pragma unroll
            for (int nt = 0; nt < 8; nt++) {
                int c0 = wn*64 + nt*8 + g;
                b[nt][0] = f2tf(Bb[(kk+q)*BS_STR + c0]);
                b[nt][1] = f2tf(Bb[(kk+q+4)*BS_STR + c0]);
            }
            #pragma unroll
            for (int mt = 0; mt < 2; mt++)
                #pragma unroll
                for (int nt = 0; nt < 8; nt++)
                    mma_tf32(acc[mt][nt], a[mt], b[nt]);
        }
    }

    // epilogue
    #pragma unroll
    for (int mt = 0; mt < 2; mt++) {
        int row = by*128 + wm*32 + mt*16 + g;
        #pragma unroll
        for (int nt = 0; nt < 8; nt++) {
            int col = bx*128 + wn*64 + nt*8 + 2*q;
            float v0 = acc[mt][nt][0], v1 = acc[mt][nt][1];
            float v2 = acc[mt][nt][2], v3 = acc[mt][nt][3];
            if (EPI) {
                float s0 = bng[col]   * rsqrtf(bnms[col]   + EPSF);
                float s1 = bng[col+1] * rsqrtf(bnms[col+1] + EPSF);
                v0 = (v0 + bias[col])   * s0;
                v1 = (v1 + bias[col+1]) * s1;
                v2 = (v2 + bias[col])   * s0;
                v3 = (v3 + bias[col+1]) * s1;
            }
            *(float2*)(Cm + (size_t)row*N + col)     = make_float2(v0, v1);
            *(float2*)(Cm + (size_t)(row+8)*N + col) = make_float2(v2, v3);
        }
    }
}

// ---------------- 3. per-head LayerNorm (+RoPE) ----------------
template<int D, bool ROPE, int H>
__global__ void ln_head_kernel(float* __restrict__ data, const float* __restrict__ gg,
                               const float* __restrict__ bb) {
    const int NV = D / 32;
    int gw = (blockIdx.x * blockDim.x + threadIdx.x) >> 5;
    int lane = threadIdx.x & 31;
    float* row = data + (size_t)gw * D;
    int s = (gw / H) % S_;
    int d0 = lane * NV;

    float vals[NV];
    #pragma unroll
    for (int i = 0; i < NV; i++) vals[i] = row[d0 + i];

    float sum = 0.f, sq = 0.f;
    #pragma unroll
    for (int i = 0; i < NV; i++) { sum += vals[i]; sq += vals[i]*vals[i]; }
    #pragma unroll
    for (int off = 16; off > 0; off >>= 1) {
        sum += __shfl_xor_sync(0xffffffffu, sum, off);
        sq  += __shfl_xor_sync(0xffffffffu, sq,  off);
    }
    float mean = sum * (1.0f / D);
    float var  = sq  * (1.0f / D) - mean * mean;
    float inv  = rsqrtf(var + EPSF);
    #pragma unroll
    for (int i = 0; i < NV; i++)
        vals[i] = (vals[i] - mean) * inv * gg[d0 + i] + bb[d0 + i];

    if (ROPE) {
        const double lg63 = log(1985.0) / 63.0;
        #pragma unroll
        for (int p = 0; p < NV/2; p++) {
            int fi = (d0 >> 1) + p;
            double geom = exp((double)fi * lg63);
            float invf = (float)(1.0 / ((double)fi + geom));
            float theta = (float)s * invf;
            float sn, cs;
            sincosf(theta, &sn, &cs);
            float x0 = vals[2*p], x1 = vals[2*p + 1];
            vals[2*p]     = x0 * cs - x1 * sn;
            vals[2*p + 1] = x1 * cs + x0 * sn;
        }
    }
    #pragma unroll
    for (int i = 0; i < NV; i++) row[d0 + i] = vals[i];
}

// ---------------- 4. flash attention with tf32 mma ----------------
// 64 queries x 64-key tiles; 8 warps (4m x 2n)
// smem strides: Q/K 132, V 104, P 68 (all conflict-free for frag patterns)
#define QS_STR 132
#define VS_STR 104
#define PS_STR 68
#define FQ_OFF 0
#define FK_OFF (64*QS_STR)            // 8448
#define FK_BUF (64*QS_STR)            // 8448
#define FV_OFF (FK_OFF + 2*FK_BUF)    // 25344
#define FV_BUF (64*VS_STR)            // 6656
#define FP_OFF (FV_OFF + 2*FV_BUF)    // 38656
#define FR_OFF (FP_OFF + 64*PS_STR)   // 43008
#define FLASH_SMEM ((FR_OFF + 128) * 4)

__global__ void __launch_bounds__(256) flash_kernel() {
    extern __shared__ float sm[];
    float* Qs = sm + FQ_OFF;
    float* Ks = sm + FK_OFF;
    float* Vs = sm + FV_OFF;
    float* Ps = sm + FP_OFF;
    float* Red = sm + FR_OFF;

    int bh = blockIdx.x;
    int b = bh / HQ_, h = bh % HQ_;
    int kv = h % HKV_;
    int s0 = blockIdx.y * 64;
    int tid = threadIdx.x;
    int lane = tid & 31, wid = tid >> 5;
    int wm = wid & 3, wn = wid >> 2;
    int g = lane >> 2, q = lane & 3;

    // load Q (once), pre-converted to tf32 bit patterns
    for (int t = tid; t < 64 * 32; t += 256) {
        int r = t >> 5, c4 = (t & 31) * 4;
        float4 qv = *(const float4*)(g_q + ((size_t)((b*S_ + s0 + r)*HQ_ + h))*DQK_ + c4);
        Qs[r*QS_STR + c4 + 0] = __uint_as_float(f2tf(qv.x));
        Qs[r*QS_STR + c4 + 1] = __uint_as_float(f2tf(qv.y));
        Qs[r*QS_STR + c4 + 2] = __uint_as_float(f2tf(qv.z));
        Qs[r*QS_STR + c4 + 3] = __uint_as_float(f2tf(qv.w));
    }

    float acc[6][4];
    #pragma unroll
    for (int nt = 0; nt < 6; nt++)
        #pragma unroll
        for (int i = 0; i < 4; i++) acc[nt][i] = 0.f;
    float rs[2] = {0.f, 0.f};

    const float scl = 0.08838834764831845f;   // 1/sqrt(128)

    // prefetch KV tile 0
    {
        const float* kb = g_k + ((size_t)(b*S_)*HKV_ + kv)*DQK_;
        const float* vb = g_v + ((size_t)(b*S_)*HKV_ + kv)*DV_;
        #pragma unroll
        for (int i = 0; i < 8; i++) {
            int f4 = tid + i*256;
            int r = f4 >> 5, c = (f4 & 31) * 4;
            cp16(Ks + r*QS_STR + c, kb + (size_t)r*HKV_*DQK_ + c);
        }
        #pragma unroll
        for (int i = 0; i < 6; i++) {
            int f4 = tid + i*256;
            int r = f4 / 24, c = (f4 % 24) * 4;
            cp16(Vs + r*VS_STR + c, vb + (size_t)r*HKV_*DV_ + c);
        }
        cp_commit();
    }

    for (int t0 = 0; t0 < 32; t0++) {
        cp_wait0();
        __syncthreads();          // K/V tile ready; Ps from prev iter fully consumed
        if (t0 + 1 < 32) {
            const float* kb = g_k + ((size_t)(b*S_ + (t0+1)*64)*HKV_ + kv)*DQK_;
            const float* vb = g_v + ((size_t)(b*S_ + (t0+1)*64)*HKV_ + kv)*DV_;
            float* kd = Ks + ((t0+1)&1)*FK_BUF;
            float* vd = Vs + ((t0+1)&1)*FV_BUF;
            #pragma unroll
            for (int i = 0; i < 8; i++) {
                int f4 = tid + i*256;
                int r = f4 >> 5, c = (f4 & 31) * 4;
                cp16(kd + r*QS_STR + c, kb + (size_t)r*HKV_*DQK_ + c);
            }
            #pragma unroll
            for (int i = 0; i < 6; i++) {
                int f4 = tid + i*256;
                int r = f4 / 24, c = (f4 % 24) * 4;
                cp16(vd + r*VS_STR + c, vb + (size_t)r*HKV_*DV_ + c);
            }
            cp_commit();
        }
        const float* Kb = Ks + (t0&1)*FK_BUF;
        const float* Vb = Vs + (t0&1)*FV_BUF;

        // S = Q K^T
        float sacc[4][4];
        #pragma unroll
        for (int nt = 0; nt < 4; nt++)
            #pragma unroll
            for (int i = 0; i < 4; i++) sacc[nt][i] = 0.f;

        #pragma unroll
        for (int kk = 0; kk < DQK_; kk += 8) {
            unsigned a[4], bfr[4][2];
            int r = wm*16 + g;
            a[0] = __float_as_uint(Qs[r*QS_STR + kk + q]);
            a[1] = __float_as_uint(Qs[(r+8)*QS_STR + kk + q]);
            a[2] = __float_as_uint(Qs[r*QS_STR + kk + q + 4]);
            a[3] = __float_as_uint(Qs[(r+8)*QS_STR + kk + q + 4]);
            #pragma unroll
            for (int nt = 0; nt < 4; nt++) {
                int key = wn*32 + nt*8 + g;
                bfr[nt][0] = f2tf(Kb[key*QS_STR + kk + q]);
                bfr[nt][1] = f2tf(Kb[key*QS_STR + kk + q + 4]);
            }
            #pragma unroll
            for (int nt = 0; nt < 4; nt++) mma_tf32(sacc[nt], a, bfr[nt]);
        }

        // p = exp(5*tanh(logit/5)); bounded -> no max tracking. Store tf32-rounded P,
        // and use the SAME rounded value in the row sum for consistency.
        #pragma unroll
        for (int nt = 0; nt < 4; nt++) {
            #pragma unroll
            for (int ci = 0; ci < 4; ci++) {
                float l = sacc[nt][ci] * scl;
                float p = __expf(5.0f * tanhf(l * 0.2f));
                unsigned pu = f2tf(p);
                float pr = __uint_as_float(pu);
                rs[ci >> 1] += pr;
                int row = wm*16 + g + ((ci >= 2) ? 8 : 0);
                int col = wn*32 + nt*8 + 2*q + (ci & 1);
                Ps[row*PS_STR + col] = pr;
            }
        }
        __syncthreads();

        // acc += P @ V
        #pragma unroll
        for (int kk = 0; kk < 64; kk += 8) {
            unsigned a[4], bfr[6][2];
            int r = wm*16 + g;
            a[0] = __float_as_uint(Ps[r*PS_STR + kk + q]);
            a[1] = __float_as_uint(Ps[(r+8)*PS_STR + kk + q]);
            a[2] = __float_as_uint(Ps[r*PS_STR + kk + q + 4]);
            a[3] = __float_as_uint(Ps[(r+8)*PS_STR + kk + q + 4]);
            #pragma unroll
            for (int nt = 0; nt < 6; nt++) {
                int dv = wn*48 + nt*8 + g;
                bfr[nt][0] = f2tf(Vb[(kk+q)*VS_STR + dv]);
                bfr[nt][1] = f2tf(Vb[(kk+q+4)*VS_STR + dv]);
            }
            #pragma unroll
            for (int nt = 0; nt < 6; nt++) mma_tf32(acc[nt], a, bfr[nt]);
        }
    }

    // row-sum reduction: quad (over q) via shfl, then across the 2 n-warps via smem
    #pragma unroll
    for (int i = 0; i < 2; i++) {
        rs[i] += __shfl_xor_sync(0xffffffffu, rs[i], 1);
        rs[i] += __shfl_xor_sync(0xffffffffu, rs[i], 2);
    }
    int row0 = wm*16 + g;
    if (q == 0) {
        Red[row0*2 + wn]     = rs[0];
        Red[(row0+8)*2 + wn] = rs[1];
    }
    __syncthreads();
    float inv0 = 1.0f / (Red[row0*2] + Red[row0*2 + 1]);
    float inv1 = 1.0f / (Red[(row0+8)*2] + Red[(row0+8)*2 + 1]);

    #pragma unroll
    for (int nt = 0; nt < 6; nt++) {
        int col = wn*48 + nt*8 + 2*q;
        size_t b0 = ((size_t)((b*S_ + s0 + row0)*HQ_ + h))*DV_ + col;
        size_t b1 = ((size_t)((b*S_ + s0 + row0 + 8)*HQ_ + h))*DV_ + col;
        *(float2*)(g_y + b0) = make_float2(acc[nt][0]*inv0, acc[nt][1]*inv0);
        *(float2*)(g_y + b1) = make_float2(acc[nt][2]*inv1, acc[nt][3]*inv1);
    }
}

// ---------------- launch ----------------
extern "C" void kernel_launch(void* const* d_in, const int* in_sizes, int n_in,
                              void* d_out, int out_size) {
    const float* x      = (const float*)d_in[0];
    const float* bn1_g  = (const float*)d_in[1];
    const float* bn1_ms = (const float*)d_in[2];
    const float* Wq     = (const float*)d_in[3];
    const float* Wk     = (const float*)d_in[4];
    const float* Wv     = (const float*)d_in[5];
    const float* qn_g   = (const float*)d_in[6];
    const float* qn_b   = (const float*)d_in[7];
    const float* kn_g   = (const float*)d_in[8];
    const float* kn_b   = (const float*)d_in[9];
    const float* vn_g   = (const float*)d_in[10];
    const float* vn_b   = (const float*)d_in[11];
    const float* Wo     = (const float*)d_in[12];
    const float* bo     = (const float*)d_in[13];
    const float* bn2_g  = (const float*)d_in[14];
    const float* bn2_ms = (const float*)d_in[15];
    float* out = (float*)d_out;

    float *ph, *pq, *pk, *pv, *py;
    cudaGetSymbolAddress((void**)&ph, g_h);
    cudaGetSymbolAddress((void**)&pq, g_q);
    cudaGetSymbolAddress((void**)&pk, g_k);
    cudaGetSymbolAddress((void**)&pv, g_v);
    cudaGetSymbolAddress((void**)&py, g_y);

    const int M = B_ * S_;
    const int gemm_smem = (2*AS_BUF + 2*BS_BUF) * 4;   // 71680 B

    cudaFuncSetAttribute(tf32gemm_kernel<false>, cudaFuncAttributeMaxDynamicSharedMemorySize, gemm_smem);
    cudaFuncSetAttribute(tf32gemm_kernel<true>,  cudaFuncAttributeMaxDynamicSharedMemorySize, gemm_smem);
    cudaFuncSetAttribute(flash_kernel, cudaFuncAttributeMaxDynamicSharedMemorySize, FLASH_SMEM);

    // 1. rms_bn1
    rmsbn1_kernel<<<(B_*S_*C_/4 + 255)/256, 256>>>(x, bn1_g, bn1_ms);

    // 2. QKV projections (tf32 tensor cores)
    tf32gemm_kernel<false><<<dim3((HQ_*DQK_)/128,  M/128), 256, gemm_smem>>>(ph, Wq, pq, M, HQ_*DQK_,  C_, nullptr, nullptr, nullptr);
    tf32gemm_kernel<false><<<dim3((HKV_*DQK_)/128, M/128), 256, gemm_smem>>>(ph, Wk, pk, M, HKV_*DQK_, C_, nullptr, nullptr, nullptr);
    tf32gemm_kernel<false><<<dim3((HKV_*DV_)/128,  M/128), 256, gemm_smem>>>(ph, Wv, pv, M, HKV_*DV_,  C_, nullptr, nullptr, nullptr);

    // 3. per-head LN (+RoPE)
    ln_head_kernel<DQK_, true,  HQ_ ><<<(B_*S_*HQ_)/8,  256>>>(pq, qn_g, qn_b);
    ln_head_kernel<DQK_, true,  HKV_><<<(B_*S_*HKV_)/8, 256>>>(pk, kn_g, kn_b);
    ln_head_kernel<DV_,  false, HKV_><<<(B_*S_*HKV_)/8, 256>>>(pv, vn_g, vn_b);

    // 4. attention (tf32 tensor cores)
    flash_kernel<<<dim3(B_*HQ_, S_/64), 256, FLASH_SMEM>>>();

    // 5. output projection + bias + rms_bn2
    tf32gemm_kernel<true><<<dim3(C_/128, M/128), 256, gemm_smem>>>(py, Wo, out, M, C_, HQ_*DV_, bo, bn2_g, bn2_ms);
}

// round 3
// speedup vs baseline: 2.5948x; 1.0427x over previous
#include <cuda_runtime.h>
#include <math.h>

#define B_ 2
#define S_ 2048
#define C_ 1536
#define HQ_ 16
#define HKV_ 4
#define DQK_ 128
#define DV_ 96
#define EPSF 1e-5f
#define NQKV 2944   // 2048 + 512 + 384

// ---------------- scratch ----------------
__device__ float g_h[B_*S_*C_];
__device__ float g_q[B_*S_*HQ_*DQK_];
__device__ float g_k[B_*S_*HKV_*DQK_];
__device__ float g_v[B_*S_*HKV_*DV_];
__device__ float g_y[B_*S_*HQ_*DV_];
__device__ float g_wqkv[C_*NQKV];      // packed tf32 Wq|Wk|Wv
__device__ float g_wo[C_*C_];          // tf32 Wo

// ---------------- helpers ----------------
__device__ __forceinline__ unsigned f2tf(float f) {
    unsigned u;
    asm("cvt.rna.tf32.f32 %0, %1;" : "=r"(u) : "f"(f));
    return u;
}
__device__ __forceinline__ float f2tff(float f) {
    return __uint_as_float(f2tf(f));
}
__device__ __forceinline__ void mma_tf32(float c[4], const unsigned a[4], const unsigned b[2]) {
    asm volatile(
        "mma.sync.aligned.m16n8k8.row.col.f32.tf32.tf32.f32 "
        "{%0,%1,%2,%3},{%4,%5,%6,%7},{%8,%9},{%0,%1,%2,%3};"
        : "+f"(c[0]), "+f"(c[1]), "+f"(c[2]), "+f"(c[3])
        : "r"(a[0]), "r"(a[1]), "r"(a[2]), "r"(a[3]), "r"(b[0]), "r"(b[1]));
}
__device__ __forceinline__ void cp16(void* smem, const void* gp) {
    unsigned s = (unsigned)__cvta_generic_to_shared(smem);
    asm volatile("cp.async.cg.shared.global [%0], [%1], 16;\n" :: "r"(s), "l"(gp));
}
__device__ __forceinline__ void cp_commit() { asm volatile("cp.async.commit_group;\n"); }
__device__ __forceinline__ void cp_wait0() { asm volatile("cp.async.wait_group 0;\n"); }

// ---------------- 0. weight pack/convert (tf32-round once per launch) --------
__global__ void pack_qkv_kernel(const float* __restrict__ Wq, const float* __restrict__ Wk,
                                const float* __restrict__ Wv) {
    int idx = (blockIdx.x * blockDim.x + threadIdx.x) * 4;
    if (idx >= C_*NQKV) return;
    int row = idx / NQKV, n = idx % NQKV;
    const float* src;
    if (n < 2048)      src = Wq + (size_t)row*2048 + n;
    else if (n < 2560) src = Wk + (size_t)row*512  + (n - 2048);
    else               src = Wv + (size_t)row*384  + (n - 2560);
    float4 v = *(const float4*)src;
    float4 o = make_float4(f2tff(v.x), f2tff(v.y), f2tff(v.z), f2tff(v.w));
    *(float4*)(g_wqkv + idx) = o;
}
__global__ void conv_wo_kernel(const float* __restrict__ Wo) {
    int idx = (blockIdx.x * blockDim.x + threadIdx.x) * 4;
    if (idx >= C_*C_) return;
    float4 v = *(const float4*)(Wo + idx);
    *(float4*)(g_wo + idx) = make_float4(f2tff(v.x), f2tff(v.y), f2tff(v.z), f2tff(v.w));
}

// ---------------- 1. rms_bn1 (tf32-rounded output) ----------------
__global__ void rmsbn1_kernel(const float* __restrict__ x, const float* __restrict__ g,
                              const float* __restrict__ ms) {
    int idx = (blockIdx.x * blockDim.x + threadIdx.x) * 4;
    if (idx >= B_*S_*C_) return;
    float4 xv = *(const float4*)(x + idx);
    int c = idx % C_;
    float4 o;
    o.x = f2tff(xv.x * g[c+0] * rsqrtf(ms[c+0] + EPSF));
    o.y = f2tff(xv.y * g[c+1] * rsqrtf(ms[c+1] + EPSF));
    o.z = f2tff(xv.z * g[c+2] * rsqrtf(ms[c+2] + EPSF));
    o.w = f2tff(xv.w * g[c+3] * rsqrtf(ms[c+3] + EPSF));
    *(float4*)(g_h + idx) = o;
}

// ---------------- 2. tf32 tensor-core GEMM 128x128x32 ----------------
// operands pre-rounded to tf32; inner loop = LDS + HMMA only
#define AS_STR 36
#define BS_STR 136
#define AS_BUF (128*AS_STR)
#define BS_BUF (32*BS_STR)

// MODE: 1 = QKV split store, 2 = bias + rms_bn2 epilogue to Cm
template<int MODE>
__global__ void __launch_bounds__(256, 2) tf32gemm_kernel(
    const float* __restrict__ A, const float* __restrict__ Bm, float* __restrict__ Cm,
    int M, int N, int K,
    const float* __restrict__ bias, const float* __restrict__ bng,
    const float* __restrict__ bnms,
    float* __restrict__ gq, float* __restrict__ gk, float* __restrict__ gv)
{
    extern __shared__ float sm[];
    float* As = sm;
    float* Bs = sm + 2*AS_BUF;

    int tid = threadIdx.x;
    int lane = tid & 31, wid = tid >> 5;
    int wm = wid & 3, wn = wid >> 2;
    int g = lane >> 2, q = lane & 3;
    int bx = blockIdx.x, by = blockIdx.y;

    float acc[2][8][4];
    #pragma unroll
    for (int mt = 0; mt < 2; mt++)
        #pragma unroll
        for (int nt = 0; nt < 8; nt++)
            #pragma unroll
            for (int i = 0; i < 4; i++) acc[mt][nt][i] = 0.f;

    const int nk = K / 32;
    {
        #pragma unroll
        for (int i = 0; i < 4; i++) {
            int f4 = tid + i*256;
            int r = f4 >> 3, c = (f4 & 7) * 4;
            cp16(As + r*AS_STR + c, A + (size_t)(by*128 + r)*K + c);
        }
        #pragma unroll
        for (int i = 0; i < 4; i++) {
            int f4 = tid + i*256;
            int r = f4 >> 5, c = (f4 & 31) * 4;
            cp16(Bs + r*BS_STR + c, Bm + (size_t)r*N + bx*128 + c);
        }
        cp_commit();
    }

    for (int kt = 0; kt < nk; kt++) {
        cp_wait0();
        __syncthreads();
        if (kt + 1 < nk) {
            float* Ad = As + ((kt+1)&1)*AS_BUF;
            float* Bd = Bs + ((kt+1)&1)*BS_BUF;
            int k0 = (kt+1)*32;
            #pragma unroll
            for (int i = 0; i < 4; i++) {
                int f4 = tid + i*256;
                int r = f4 >> 3, c = (f4 & 7) * 4;
                cp16(Ad + r*AS_STR + c, A + (size_t)(by*128 + r)*K + k0 + c);
            }
            #pragma unroll
            for (int i = 0; i < 4; i++) {
                int f4 = tid + i*256;
                int r = f4 >> 5, c = (f4 & 31) * 4;
                cp16(Bd + r*BS_STR + c, Bm + (size_t)(k0 + r)*N + bx*128 + c);
            }
            cp_commit();
        }
        const float* Ab = As + (kt&1)*AS_BUF;
        const float* Bb = Bs + (kt&1)*BS_BUF;
        #pragma unroll
        for (int kk = 0; kk < 32; kk += 8) {
            unsigned a[2][4], b[8][2];
            #pragma unroll
            for (int mt = 0; mt < 2; mt++) {
                int r = wm*32 + mt*16 + g;
                a[mt][0] = __float_as_uint(Ab[r*AS_STR + kk + q]);
                a[mt][1] = __float_as_uint(Ab[(r+8)*AS_STR + kk + q]);
                a[mt][2] = __float_as_uint(Ab[r*AS_STR + kk + q + 4]);
                a[mt][3] = __float_as_uint(Ab[(r+8)*AS_STR + kk + q + 4]);
            }
            #pragma unroll
            for (int nt = 0; nt < 8; nt++) {
                int c0 = wn*64 + nt*8 + g;
                b[nt][0] = __float_as_uint(Bb[(kk+q)*BS_STR + c0]);
                b[nt][1] = __float_as_uint(Bb[(kk+q+4)*BS_STR + c0]);
            }
            #pragma unroll
            for (int mt = 0; mt < 2; mt++)
                #pragma unroll
                for (int nt = 0; nt < 8; nt++)
                    mma_tf32(acc[mt][nt], a[mt], b[nt]);
        }
    }

    #pragma unroll
    for (int mt = 0; mt < 2; mt++) {
        int row = by*128 + wm*32 + mt*16 + g;
        #pragma unroll
        for (int nt = 0; nt < 8; nt++) {
            int col = bx*128 + wn*64 + nt*8 + 2*q;
            float v0 = acc[mt][nt][0], v1 = acc[mt][nt][1];
            float v2 = acc[mt][nt][2], v3 = acc[mt][nt][3];
            if (MODE == 2) {
                float s0 = bng[col]   * rsqrtf(bnms[col]   + EPSF);
                float s1 = bng[col+1] * rsqrtf(bnms[col+1] + EPSF);
                v0 = (v0 + bias[col])   * s0;
                v1 = (v1 + bias[col+1]) * s1;
                v2 = (v2 + bias[col])   * s0;
                v3 = (v3 + bias[col+1]) * s1;
                *(float2*)(Cm + (size_t)row*N + col)     = make_float2(v0, v1);
                *(float2*)(Cm + (size_t)(row+8)*N + col) = make_float2(v2, v3);
            } else {
                // split store to q/k/v (8-wide tiles never straddle 2048/2560)
                float *d0, *d1;
                if (col < 2048) {
                    d0 = gq + (size_t)row*2048 + col;
                    d1 = gq + (size_t)(row+8)*2048 + col;
                } else if (col < 2560) {
                    d0 = gk + (size_t)row*512 + (col - 2048);
                    d1 = gk + (size_t)(row+8)*512 + (col - 2048);
                } else {
                    d0 = gv + (size_t)row*384 + (col - 2560);
                    d1 = gv + (size_t)(row+8)*384 + (col - 2560);
                }
                *(float2*)d0 = make_float2(v0, v1);
                *(float2*)d1 = make_float2(v2, v3);
            }
        }
    }
}

// ---------------- 3. per-head LayerNorm (+RoPE), tf32-rounded output ----------
template<int D, bool ROPE, int H>
__global__ void ln_head_kernel(float* __restrict__ data, const float* __restrict__ gg,
                               const float* __restrict__ bb) {
    const int NV = D / 32;
    int gw = (blockIdx.x * blockDim.x + threadIdx.x) >> 5;
    int lane = threadIdx.x & 31;
    float* row = data + (size_t)gw * D;
    int s = (gw / H) % S_;
    int d0 = lane * NV;

    float vals[NV];
    #pragma unroll
    for (int i = 0; i < NV; i++) vals[i] = row[d0 + i];

    float sum = 0.f, sq = 0.f;
    #pragma unroll
    for (int i = 0; i < NV; i++) { sum += vals[i]; sq += vals[i]*vals[i]; }
    #pragma unroll
    for (int off = 16; off > 0; off >>= 1) {
        sum += __shfl_xor_sync(0xffffffffu, sum, off);
        sq  += __shfl_xor_sync(0xffffffffu, sq,  off);
    }
    float mean = sum * (1.0f / D);
    float var  = sq  * (1.0f / D) - mean * mean;
    float inv  = rsqrtf(var + EPSF);
    #pragma unroll
    for (int i = 0; i < NV; i++)
        vals[i] = (vals[i] - mean) * inv * gg[d0 + i] + bb[d0 + i];

    if (ROPE) {
        const double lg63 = log(1985.0) / 63.0;
        #pragma unroll
        for (int p = 0; p < NV/2; p++) {
            int fi = (d0 >> 1) + p;
            double geom = exp((double)fi * lg63);
            float invf = (float)(1.0 / ((double)fi + geom));
            float theta = (float)s * invf;
            float sn, cs;
            sincosf(theta, &sn, &cs);
            float x0 = vals[2*p], x1 = vals[2*p + 1];
            vals[2*p]     = x0 * cs - x1 * sn;
            vals[2*p + 1] = x1 * cs + x0 * sn;
        }
    }
    #pragma unroll
    for (int i = 0; i < NV; i++) row[d0 + i] = f2tff(vals[i]);
}

// ---------------- 4. flash attention, all operands pre-tf32 ----------------
#define QS_STR 132
#define VS_STR 104
#define PS_STR 68
#define FQ_OFF 0
#define FK_OFF (64*QS_STR)
#define FK_BUF (64*QS_STR)
#define FV_OFF (FK_OFF + 2*FK_BUF)
#define FV_BUF (64*VS_STR)
#define FP_OFF (FV_OFF + 2*FV_BUF)
#define FR_OFF (FP_OFF + 64*PS_STR)
#define FLASH_SMEM ((FR_OFF + 128) * 4)

__global__ void __launch_bounds__(256) flash_kernel() {
    extern __shared__ float sm[];
    float* Qs = sm + FQ_OFF;
    float* Ks = sm + FK_OFF;
    float* Vs = sm + FV_OFF;
    float* Ps = sm + FP_OFF;
    float* Red = sm + FR_OFF;

    int bh = blockIdx.x;
    int b = bh / HQ_, h = bh % HQ_;
    int kv = h % HKV_;
    int s0 = blockIdx.y * 64;
    int tid = threadIdx.x;
    int lane = tid & 31, wid = tid >> 5;
    int wm = wid & 3, wn = wid >> 2;
    int g = lane >> 2, q = lane & 3;

    float acc[6][4];
    #pragma unroll
    for (int nt = 0; nt < 6; nt++)
        #pragma unroll
        for (int i = 0; i < 4; i++) acc[nt][i] = 0.f;
    float rs[2] = {0.f, 0.f};

    const float scl = 0.08838834764831845f;

    // prefetch Q + KV tile 0 (all already tf32-rounded in gmem)
    {
        const float* qb = g_q + ((size_t)((b*S_ + s0)*HQ_ + h))*DQK_;
        #pragma unroll
        for (int i = 0; i < 8; i++) {
            int f4 = tid + i*256;
            int r = f4 >> 5, c = (f4 & 31) * 4;
            cp16(Qs + r*QS_STR + c, qb + (size_t)r*HQ_*DQK_ + c);
        }
        const float* kb = g_k + ((size_t)(b*S_)*HKV_ + kv)*DQK_;
        const float* vb = g_v + ((size_t)(b*S_)*HKV_ + kv)*DV_;
        #pragma unroll
        for (int i = 0; i < 8; i++) {
            int f4 = tid + i*256;
            int r = f4 >> 5, c = (f4 & 31) * 4;
            cp16(Ks + r*QS_STR + c, kb + (size_t)r*HKV_*DQK_ + c);
        }
        #pragma unroll
        for (int i = 0; i < 6; i++) {
            int f4 = tid + i*256;
            int r = f4 / 24, c = (f4 % 24) * 4;
            cp16(Vs + r*VS_STR + c, vb + (size_t)r*HKV_*DV_ + c);
        }
        cp_commit();
    }

    for (int t0 = 0; t0 < 32; t0++) {
        cp_wait0();
        __syncthreads();
        if (t0 + 1 < 32) {
            const float* kb = g_k + ((size_t)(b*S_ + (t0+1)*64)*HKV_ + kv)*DQK_;
            const float* vb = g_v + ((size_t)(b*S_ + (t0+1)*64)*HKV_ + kv)*DV_;
            float* kd = Ks + ((t0+1)&1)*FK_BUF;
            float* vd = Vs + ((t0+1)&1)*FV_BUF;
            #pragma unroll
            for (int i = 0; i < 8; i++) {
                int f4 = tid + i*256;
                int r = f4 >> 5, c = (f4 & 31) * 4;
                cp16(kd + r*QS_STR + c, kb + (size_t)r*HKV_*DQK_ + c);
            }
            #pragma unroll
            for (int i = 0; i < 6; i++) {
                int f4 = tid + i*256;
                int r = f4 / 24, c = (f4 % 24) * 4;
                cp16(vd + r*VS_STR + c, vb + (size_t)r*HKV_*DV_ + c);
            }
            cp_commit();
        }
        const float* Kb = Ks + (t0&1)*FK_BUF;
        const float* Vb = Vs + (t0&1)*FV_BUF;

        float sacc[4][4];
        #pragma unroll
        for (int nt = 0; nt < 4; nt++)
            #pragma unroll
            for (int i = 0; i < 4; i++) sacc[nt][i] = 0.f;

        #pragma unroll
        for (int kk = 0; kk < DQK_; kk += 8) {
            unsigned a[4], bfr[4][2];
            int r = wm*16 + g;
            a[0] = __float_as_uint(Qs[r*QS_STR + kk + q]);
            a[1] = __float_as_uint(Qs[(r+8)*QS_STR + kk + q]);
            a[2] = __float_as_uint(Qs[r*QS_STR + kk + q + 4]);
            a[3] = __float_as_uint(Qs[(r+8)*QS_STR + kk + q + 4]);
            #pragma unroll
            for (int nt = 0; nt < 4; nt++) {
                int key = wn*32 + nt*8 + g;
                bfr[nt][0] = __float_as_uint(Kb[key*QS_STR + kk + q]);
                bfr[nt][1] = __float_as_uint(Kb[key*QS_STR + kk + q + 4]);
            }
            #pragma unroll
            for (int nt = 0; nt < 4; nt++) mma_tf32(sacc[nt], a, bfr[nt]);
        }

        #pragma unroll
        for (int nt = 0; nt < 4; nt++) {
            #pragma unroll
            for (int ci = 0; ci < 4; ci++) {
                float l = sacc[nt][ci] * scl;
                float p = __expf(5.0f * tanhf(l * 0.2f));
                float pr = f2tff(p);
                rs[ci >> 1] += pr;
                int row = wm*16 + g + ((ci >= 2) ? 8 : 0);
                int col = wn*32 + nt*8 + 2*q + (ci & 1);
                Ps[row*PS_STR + col] = pr;
            }
        }
        __syncthreads();

        #pragma unroll
        for (int kk = 0; kk < 64; kk += 8) {
            unsigned a[4], bfr[6][2];
            int r = wm*16 + g;
            a[0] = __float_as_uint(Ps[r*PS_STR + kk + q]);
            a[1] = __float_as_uint(Ps[(r+8)*PS_STR + kk + q]);
            a[2] = __float_as_uint(Ps[r*PS_STR + kk + q + 4]);
            a[3] = __float_as_uint(Ps[(r+8)*PS_STR + kk + q + 4]);
            #pragma unroll
            for (int nt = 0; nt < 6; nt++) {
                int dv = wn*48 + nt*8 + g;
                bfr[nt][0] = __float_as_uint(Vb[(kk+q)*VS_STR + dv]);
                bfr[nt][1] = __float_as_uint(Vb[(kk+q+4)*VS_STR + dv]);
            }
            #pragma unroll
            for (int nt = 0; nt < 6; nt++) mma_tf32(acc[nt], a, bfr[nt]);
        }
    }

    #pragma unroll
    for (int i = 0; i < 2; i++) {
        rs[i] += __shfl_xor_sync(0xffffffffu, rs[i], 1);
        rs[i] += __shfl_xor_sync(0xffffffffu, rs[i], 2);
    }
    int row0 = wm*16 + g;
    if (q == 0) {
        Red[row0*2 + wn]     = rs[0];
        Red[(row0+8)*2 + wn] = rs[1];
    }
    __syncthreads();
    float inv0 = 1.0f / (Red[row0*2] + Red[row0*2 + 1]);
    float inv1 = 1.0f / (Red[(row0+8)*2] + Red[(row0+8)*2 + 1]);

    // y is consumed as tf32 A-operand of the Wo GEMM -> round here
    #pragma unroll
    for (int nt = 0; nt < 6; nt++) {
        int col = wn*48 + nt*8 + 2*q;
        size_t b0 = ((size_t)((b*S_ + s0 + row0)*HQ_ + h))*DV_ + col;
        size_t b1 = ((size_t)((b*S_ + s0 + row0 + 8)*HQ_ + h))*DV_ + col;
        *(float2*)(g_y + b0) = make_float2(f2tff(acc[nt][0]*inv0), f2tff(acc[nt][1]*inv0));
        *(float2*)(g_y + b1) = make_float2(f2tff(acc[nt][2]*inv1), f2tff(acc[nt][3]*inv1));
    }
}

// ---------------- launch ----------------
extern "C" void kernel_launch(void* const* d_in, const int* in_sizes, int n_in,
                              void* d_out, int out_size) {
    const float* x      = (const float*)d_in[0];
    const float* bn1_g  = (const float*)d_in[1];
    const float* bn1_ms = (const float*)d_in[2];
    const float* Wq     = (const float*)d_in[3];
    const float* Wk     = (const float*)d_in[4];
    const float* Wv     = (const float*)d_in[5];
    const float* qn_g   = (const float*)d_in[6];
    const float* qn_b   = (const float*)d_in[7];
    const float* kn_g   = (const float*)d_in[8];
    const float* kn_b   = (const float*)d_in[9];
    const float* vn_g   = (const float*)d_in[10];
    const float* vn_b   = (const float*)d_in[11];
    const float* Wo     = (const float*)d_in[12];
    const float* bo     = (const float*)d_in[13];
    const float* bn2_g  = (const float*)d_in[14];
    const float* bn2_ms = (const float*)d_in[15];
    float* out = (float*)d_out;

    float *ph, *pq, *pk, *pv, *py, *pwqkv, *pwo;
    cudaGetSymbolAddress((void**)&ph, g_h);
    cudaGetSymbolAddress((void**)&pq, g_q);
    cudaGetSymbolAddress((void**)&pk, g_k);
    cudaGetSymbolAddress((void**)&pv, g_v);
    cudaGetSymbolAddress((void**)&py, g_y);
    cudaGetSymbolAddress((void**)&pwqkv, g_wqkv);
    cudaGetSymbolAddress((void**)&pwo, g_wo);

    const int M = B_ * S_;
    const int gemm_smem = (2*AS_BUF + 2*BS_BUF) * 4;

    cudaFuncSetAttribute(tf32gemm_kernel<1>, cudaFuncAttributeMaxDynamicSharedMemorySize, gemm_smem);
    cudaFuncSetAttribute(tf32gemm_kernel<2>, cudaFuncAttributeMaxDynamicSharedMemorySize, gemm_smem);
    cudaFuncSetAttribute(flash_kernel, cudaFuncAttributeMaxDynamicSharedMemorySize, FLASH_SMEM);

    // 0. weight packing + conversion
    pack_qkv_kernel<<<(C_*NQKV/4 + 255)/256, 256>>>(Wq, Wk, Wv);
    conv_wo_kernel<<<(C_*C_/4 + 255)/256, 256>>>(Wo);

    // 1. rms_bn1
    rmsbn1_kernel<<<(B_*S_*C_/4 + 255)/256, 256>>>(x, bn1_g, bn1_ms);

    // 2. fused QKV projection
    tf32gemm_kernel<1><<<dim3(NQKV/128, M/128), 256, gemm_smem>>>(
        ph, pwqkv, nullptr, M, NQKV, C_, nullptr, nullptr, nullptr, pq, pk, pv);

    // 3. per-head LN (+RoPE), outputs tf32-rounded
    ln_head_kernel<DQK_, true,  HQ_ ><<<(B_*S_*HQ_)/8,  256>>>(pq, qn_g, qn_b);
    ln_head_kernel<DQK_, true,  HKV_><<<(B_*S_*HKV_)/8, 256>>>(pk, kn_g, kn_b);
    ln_head_kernel<DV_,  false, HKV_><<<(B_*S_*HKV_)/8, 256>>>(pv, vn_g, vn_b);

    // 4. attention
    flash_kernel<<<dim3(B_*HQ_, S_/64), 256, FLASH_SMEM>>>();

    // 5. output projection + bias + rms_bn2
    tf32gemm_kernel<2><<<dim3(C_/128, M/128), 256, gemm_smem>>>(
        py, pwo, out, M, C_, HQ_*DV_, bo, bn2_g, bn2_ms, nullptr, nullptr, nullptr);
}

// round 4
// speedup vs baseline: 2.8170x; 1.0856x over previous
#include <cuda_runtime.h>
#include <math.h>

#define B_ 2
#define S_ 2048
#define C_ 1536
#define HQ_ 16
#define HKV_ 4
#define DQK_ 128
#define DV_ 96
#define EPSF 1e-5f
#define NQKV 2944   // 2048 + 512 + 384

// ---------------- scratch ----------------
__device__ float g_h[B_*S_*C_];
__device__ float g_q[B_*S_*HQ_*DQK_];
__device__ float g_k[B_*S_*HKV_*DQK_];
__device__ float g_v[B_*S_*HKV_*DV_];
__device__ float g_y[B_*S_*HQ_*DV_];
__device__ float g_wqkv[NQKV*C_];      // tf32 Wq|Wk|Wv, TRANSPOSED [N][K]
__device__ float g_wo[C_*C_];          // tf32 Wo, TRANSPOSED [N][K]

// ---------------- helpers ----------------
__device__ __forceinline__ unsigned f2tf(float f) {
    unsigned u;
    asm("cvt.rna.tf32.f32 %0, %1;" : "=r"(u) : "f"(f));
    return u;
}
__device__ __forceinline__ float f2tff(float f) { return __uint_as_float(f2tf(f)); }
__device__ __forceinline__ void mma_tf32(float c[4], const unsigned a[4], const unsigned b[2]) {
    asm volatile(
        "mma.sync.aligned.m16n8k8.row.col.f32.tf32.tf32.f32 "
        "{%0,%1,%2,%3},{%4,%5,%6,%7},{%8,%9},{%0,%1,%2,%3};"
        : "+f"(c[0]), "+f"(c[1]), "+f"(c[2]), "+f"(c[3])
        : "r"(a[0]), "r"(a[1]), "r"(a[2]), "r"(a[3]), "r"(b[0]), "r"(b[1]));
}
#define LDSM4(d, addr) \
    asm volatile("ldmatrix.sync.aligned.m8n8.x4.shared.b16 {%0,%1,%2,%3}, [%4];" \
        : "=r"((d)[0]), "=r"((d)[1]), "=r"((d)[2]), "=r"((d)[3]) : "r"(addr))
__device__ __forceinline__ unsigned sm_u32(const void* p) {
    return (unsigned)__cvta_generic_to_shared(p);
}
__device__ __forceinline__ void cp16(void* smem, const void* gp) {
    unsigned s = sm_u32(smem);
    asm volatile("cp.async.cg.shared.global [%0], [%1], 16;\n" :: "r"(s), "l"(gp));
}
__device__ __forceinline__ void cp_commit() { asm volatile("cp.async.commit_group;\n"); }
__device__ __forceinline__ void cp_wait0() { asm volatile("cp.async.wait_group 0;\n"); }

// ---------------- 0. tiled transpose + tf32 round: dst[n][k] = tf32(src[k][n]) ----
__global__ void transpose_tf32(const float* __restrict__ src, float* __restrict__ dst,
                               int R, int Cc) {   // src [R][Cc], dst [Cc][R]
    __shared__ float tile[32][33];
    int x = blockIdx.x*32 + threadIdx.x;
    int y0 = blockIdx.y*32;
    #pragma unroll
    for (int j = threadIdx.y; j < 32; j += 8)
        tile[j][threadIdx.x] = src[(size_t)(y0+j)*Cc + x];
    __syncthreads();
    int xo = blockIdx.y*32 + threadIdx.x;
    int yo0 = blockIdx.x*32;
    #pragma unroll
    for (int j = threadIdx.y; j < 32; j += 8)
        dst[(size_t)(yo0+j)*R + xo] = f2tff(tile[threadIdx.x][j]);
}

// ---------------- 1. rms_bn1 (tf32-rounded output) ----------------
__global__ void rmsbn1_kernel(const float* __restrict__ x, const float* __restrict__ g,
                              const float* __restrict__ ms) {
    int idx = (blockIdx.x * blockDim.x + threadIdx.x) * 4;
    if (idx >= B_*S_*C_) return;
    float4 xv = *(const float4*)(x + idx);
    int c = idx % C_;
    float4 o;
    o.x = f2tff(xv.x * g[c+0] * rsqrtf(ms[c+0] + EPSF));
    o.y = f2tff(xv.y * g[c+1] * rsqrtf(ms[c+1] + EPSF));
    o.z = f2tff(xv.z * g[c+2] * rsqrtf(ms[c+2] + EPSF));
    o.w = f2tff(xv.w * g[c+3] * rsqrtf(ms[c+3] + EPSF));
    *(float4*)(g_h + idx) = o;
}

// ---------------- 2. tf32 GEMM 128x128x32, ldmatrix feeds, B transposed [N][K] ----
#define AS_STR 36
#define BS_STR 36
#define AS_BUF (128*AS_STR)
#define BS_BUF (128*BS_STR)

// MODE: 1 = QKV split store, 2 = bias + rms_bn2 epilogue
template<int MODE>
__global__ void __launch_bounds__(256, 2) tf32gemm_kernel(
    const float* __restrict__ A, const float* __restrict__ Bt, float* __restrict__ Cm,
    int M, int N, int K,
    const float* __restrict__ bias, const float* __restrict__ bng,
    const float* __restrict__ bnms,
    float* __restrict__ gq, float* __restrict__ gk, float* __restrict__ gv)
{
    extern __shared__ float sm[];
    float* As = sm;
    float* Bs = sm + 2*AS_BUF;

    int tid = threadIdx.x;
    int lane = tid & 31, wid = tid >> 5;
    int wm = wid & 3, wn = wid >> 2;
    int g = lane >> 2, q = lane & 3;
    int bx = blockIdx.x, by = blockIdx.y;

    int t7 = lane & 7, qb0 = (lane >> 3) & 1, qb1 = (lane >> 4) & 1;
    unsigned aoff[2], boff[4];
    #pragma unroll
    for (int mt = 0; mt < 2; mt++)
        aoff[mt] = ((wm*32 + mt*16 + qb0*8 + t7)*AS_STR + qb1*4)*4;
    #pragma unroll
    for (int nt2 = 0; nt2 < 4; nt2++)
        boff[nt2] = ((wn*64 + nt2*16 + qb1*8 + t7)*BS_STR + qb0*4)*4;

    float acc[2][8][4];
    #pragma unroll
    for (int mt = 0; mt < 2; mt++)
        #pragma unroll
        for (int nt = 0; nt < 8; nt++)
            #pragma unroll
            for (int i = 0; i < 4; i++) acc[mt][nt][i] = 0.f;

    const int nk = K / 32;
    {
        #pragma unroll
        for (int i = 0; i < 4; i++) {
            int f4 = tid + i*256;
            int r = f4 >> 3, c = (f4 & 7) * 4;
            cp16(As + r*AS_STR + c, A + (size_t)(by*128 + r)*K + c);
            cp16(Bs + r*BS_STR + c, Bt + (size_t)(bx*128 + r)*K + c);
        }
        cp_commit();
    }

    for (int kt = 0; kt < nk; kt++) {
        cp_wait0();
        __syncthreads();
        if (kt + 1 < nk) {
            float* Ad = As + ((kt+1)&1)*AS_BUF;
            float* Bd = Bs + ((kt+1)&1)*BS_BUF;
            int k0 = (kt+1)*32;
            #pragma unroll
            for (int i = 0; i < 4; i++) {
                int f4 = tid + i*256;
                int r = f4 >> 3, c = (f4 & 7) * 4;
                cp16(Ad + r*AS_STR + c, A + (size_t)(by*128 + r)*K + k0 + c);
                cp16(Bd + r*BS_STR + c, Bt + (size_t)(bx*128 + r)*K + k0 + c);
            }
            cp_commit();
        }
        unsigned uA = sm_u32(As + (kt&1)*AS_BUF);
        unsigned uB = sm_u32(Bs + (kt&1)*BS_BUF);
        #pragma unroll
        for (int kk = 0; kk < 32; kk += 8) {
            unsigned a[2][4], b[4][4];
            LDSM4(a[0], uA + aoff[0] + kk*4);
            LDSM4(a[1], uA + aoff[1] + kk*4);
            #pragma unroll
            for (int nt2 = 0; nt2 < 4; nt2++) LDSM4(b[nt2], uB + boff[nt2] + kk*4);
            #pragma unroll
            for (int mt = 0; mt < 2; mt++)
                #pragma unroll
                for (int nt = 0; nt < 8; nt++)
                    mma_tf32(acc[mt][nt], a[mt], &b[nt>>1][(nt&1)*2]);
        }
    }

    #pragma unroll
    for (int mt = 0; mt < 2; mt++) {
        int row = by*128 + wm*32 + mt*16 + g;
        #pragma unroll
        for (int nt = 0; nt < 8; nt++) {
            int col = bx*128 + wn*64 + nt*8 + 2*q;
            float v0 = acc[mt][nt][0], v1 = acc[mt][nt][1];
            float v2 = acc[mt][nt][2], v3 = acc[mt][nt][3];
            if (MODE == 2) {
                float s0 = bng[col]   * rsqrtf(bnms[col]   + EPSF);
                float s1 = bng[col+1] * rsqrtf(bnms[col+1] + EPSF);
                v0 = (v0 + bias[col])   * s0;
                v1 = (v1 + bias[col+1]) * s1;
                v2 = (v2 + bias[col])   * s0;
                v3 = (v3 + bias[col+1]) * s1;
                *(float2*)(Cm + (size_t)row*N + col)     = make_float2(v0, v1);
                *(float2*)(Cm + (size_t)(row+8)*N + col) = make_float2(v2, v3);
            } else {
                float *d0, *d1;
                if (col < 2048) {
                    d0 = gq + (size_t)row*2048 + col;
                    d1 = gq + (size_t)(row+8)*2048 + col;
                } else if (col < 2560) {
                    d0 = gk + (size_t)row*512 + (col - 2048);
                    d1 = gk + (size_t)(row+8)*512 + (col - 2048);
                } else {
                    d0 = gv + (size_t)row*384 + (col - 2560);
                    d1 = gv + (size_t)(row+8)*384 + (col - 2560);
                }
                *(float2*)d0 = make_float2(v0, v1);
                *(float2*)d1 = make_float2(v2, v3);
            }
        }
    }
}

// ---------------- 3. per-head LayerNorm (+RoPE), tf32-rounded output ----------
template<int D, bool ROPE, int H>
__global__ void ln_head_kernel(float* __restrict__ data, const float* __restrict__ gg,
                               const float* __restrict__ bb) {
    const int NV = D / 32;
    int gw = (blockIdx.x * blockDim.x + threadIdx.x) >> 5;
    int lane = threadIdx.x & 31;
    float* row = data + (size_t)gw * D;
    int s = (gw / H) % S_;
    int d0 = lane * NV;

    float vals[NV];
    #pragma unroll
    for (int i = 0; i < NV; i++) vals[i] = row[d0 + i];

    float sum = 0.f, sq = 0.f;
    #pragma unroll
    for (int i = 0; i < NV; i++) { sum += vals[i]; sq += vals[i]*vals[i]; }
    #pragma unroll
    for (int off = 16; off > 0; off >>= 1) {
        sum += __shfl_xor_sync(0xffffffffu, sum, off);
        sq  += __shfl_xor_sync(0xffffffffu, sq,  off);
    }
    float mean = sum * (1.0f / D);
    float var  = sq  * (1.0f / D) - mean * mean;
    float inv  = rsqrtf(var + EPSF);
    #pragma unroll
    for (int i = 0; i < NV; i++)
        vals[i] = (vals[i] - mean) * inv * gg[d0 + i] + bb[d0 + i];

    if (ROPE) {
        const double lg63 = log(1985.0) / 63.0;
        #pragma unroll
        for (int p = 0; p < NV/2; p++) {
            int fi = (d0 >> 1) + p;
            double geom = exp((double)fi * lg63);
            float invf = (float)(1.0 / ((double)fi + geom));
            float theta = (float)s * invf;
            float sn, cs;
            sincosf(theta, &sn, &cs);
            float x0 = vals[2*p], x1 = vals[2*p + 1];
            vals[2*p]     = x0 * cs - x1 * sn;
            vals[2*p + 1] = x1 * cs + x0 * sn;
        }
    }
    #pragma unroll
    for (int i = 0; i < NV; i++) row[d0 + i] = f2tff(vals[i]);
}

// ---------------- 4. flash attention: 512 thr, 16 warps (4m x 4n), ldmatrix ------
#define QS_STR 132
#define VS_STR 104
#define PS_STR 68
#define FQ_OFF 0
#define FK_OFF (64*QS_STR)
#define FK_BUF (64*QS_STR)
#define FV_OFF (FK_OFF + 2*FK_BUF)
#define FV_BUF (64*VS_STR)
#define FP_OFF (FV_OFF + 2*FV_BUF)
#define FR_OFF (FP_OFF + 64*PS_STR)
#define FLASH_SMEM ((FR_OFF + 256) * 4)

__global__ void __launch_bounds__(512) flash_kernel() {
    extern __shared__ float sm[];
    float* Qs = sm + FQ_OFF;
    float* Ks = sm + FK_OFF;
    float* Vs = sm + FV_OFF;
    float* Ps = sm + FP_OFF;
    float* Red = sm + FR_OFF;

    int bh = blockIdx.x;
    int b = bh / HQ_, h = bh % HQ_;
    int kv = h % HKV_;
    int s0 = blockIdx.y * 64;
    int tid = threadIdx.x;
    int lane = tid & 31, wid = tid >> 5;
    int wm = wid & 3, wn = wid >> 2;          // 4 x 4 warp grid
    int g = lane >> 2, q = lane & 3;
    int t7 = lane & 7, qb0 = (lane >> 3) & 1, qb1 = (lane >> 4) & 1;

    unsigned qoff = ((wm*16 + qb0*8 + t7)*QS_STR + qb1*4)*4;   // Q A-frag
    unsigned koff = ((wn*16 + qb1*8 + t7)*QS_STR + qb0*4)*4;   // K B-frag (n-major)
    unsigned poff = ((wm*16 + qb0*8 + t7)*PS_STR + qb1*4)*4;   // P A-frag
    unsigned uQ = sm_u32(Qs) + qoff;
    unsigned uP = sm_u32(Ps) + poff;

    float acc[3][4];
    #pragma unroll
    for (int nt = 0; nt < 3; nt++)
        #pragma unroll
        for (int i = 0; i < 4; i++) acc[nt][i] = 0.f;
    float rs[2] = {0.f, 0.f};

    const float scl = 0.08838834764831845f;   // 1/sqrt(128)

    // prefetch Q + KV tile 0
    {
        const float* qb = g_q + ((size_t)((b*S_ + s0)*HQ_ + h))*DQK_;
        const float* kb = g_k + ((size_t)(b*S_)*HKV_ + kv)*DQK_;
        const float* vb = g_v + ((size_t)(b*S_)*HKV_ + kv)*DV_;
        #pragma unroll
        for (int i = 0; i < 4; i++) {
            int f4 = tid + i*512;
            int r = f4 >> 5, c = (f4 & 31) * 4;
            cp16(Qs + r*QS_STR + c, qb + (size_t)r*HQ_*DQK_ + c);
            cp16(Ks + r*QS_STR + c, kb + (size_t)r*HKV_*DQK_ + c);
        }
        #pragma unroll
        for (int i = 0; i < 3; i++) {
            int f4 = tid + i*512;
            int r = f4 / 24, c = (f4 % 24) * 4;
            cp16(Vs + r*VS_STR + c, vb + (size_t)r*HKV_*DV_ + c);
        }
        cp_commit();
    }

    int prow = wm*16 + g;
    int pcol = wn*16 + 2*q;

    for (int t0 = 0; t0 < 32; t0++) {
        cp_wait0();
        __syncthreads();
        if (t0 + 1 < 32) {
            const float* kb = g_k + ((size_t)(b*S_ + (t0+1)*64)*HKV_ + kv)*DQK_;
            const float* vb = g_v + ((size_t)(b*S_ + (t0+1)*64)*HKV_ + kv)*DV_;
            float* kd = Ks + ((t0+1)&1)*FK_BUF;
            float* vd = Vs + ((t0+1)&1)*FV_BUF;
            #pragma unroll
            for (int i = 0; i < 4; i++) {
                int f4 = tid + i*512;
                int r = f4 >> 5, c = (f4 & 31) * 4;
                cp16(kd + r*QS_STR + c, kb + (size_t)r*HKV_*DQK_ + c);
            }
            #pragma unroll
            for (int i = 0; i < 3; i++) {
                int f4 = tid + i*512;
                int r = f4 / 24, c = (f4 % 24) * 4;
                cp16(vd + r*VS_STR + c, vb + (size_t)r*HKV_*DV_ + c);
            }
            cp_commit();
        }
        unsigned uK = sm_u32(Ks + (t0&1)*FK_BUF) + koff;
        const float* Vb = Vs + (t0&1)*FV_BUF;

        // S = Q K^T (warp: 16 rows x 16 keys)
        float sacc[2][4];
        #pragma unroll
        for (int nt = 0; nt < 2; nt++)
            #pragma unroll
            for (int i = 0; i < 4; i++) sacc[nt][i] = 0.f;

        #pragma unroll
        for (int kk = 0; kk < DQK_; kk += 8) {
            unsigned aq[4], bk[4];
            LDSM4(aq, uQ + kk*4);
            LDSM4(bk, uK + kk*4);
            mma_tf32(sacc[0], aq, &bk[0]);
            mma_tf32(sacc[1], aq, &bk[2]);
        }

        // p = exp(5*tanh(l/5)) via u = e^{0.4 l}: tanh = (u-1)/(u+1)
        #pragma unroll
        for (int nt = 0; nt < 2; nt++) {
            #pragma unroll
            for (int ci = 0; ci < 4; ci++) {
                float l = sacc[nt][ci] * scl;
                float u = __expf(0.4f * l);
                float t = __fdividef(u - 1.0f, u + 1.0f);
                float p = __expf(5.0f * t);
                float pr = f2tff(p);
                rs[ci >> 1] += pr;
                int row = prow + ((ci >= 2) ? 8 : 0);
                int col = pcol + nt*8 + (ci & 1);
                Ps[row*PS_STR + col] = pr;
            }
        }
        __syncthreads();

        // acc += P @ V (warp: 16 rows x 24 dv)
        #pragma unroll
        for (int kk = 0; kk < 64; kk += 8) {
            unsigned ap[4], bv[3][2];
            LDSM4(ap, uP + kk*4);
            #pragma unroll
            for (int nt = 0; nt < 3; nt++) {
                int dv = wn*24 + nt*8 + g;
                bv[nt][0] = __float_as_uint(Vb[(kk+q)*VS_STR + dv]);
                bv[nt][1] = __float_as_uint(Vb[(kk+q+4)*VS_STR + dv]);
            }
            #pragma unroll
            for (int nt = 0; nt < 3; nt++) mma_tf32(acc[nt], ap, bv[nt]);
        }
    }

    // row sums: reduce over q lanes, then across the 4 wn warps via smem
    #pragma unroll
    for (int i = 0; i < 2; i++) {
        rs[i] += __shfl_xor_sync(0xffffffffu, rs[i], 1);
        rs[i] += __shfl_xor_sync(0xffffffffu, rs[i], 2);
    }
    if (q == 0) {
        Red[prow*4 + wn]     = rs[0];
        Red[(prow+8)*4 + wn] = rs[1];
    }
    __syncthreads();
    float inv0 = 1.0f / (Red[prow*4] + Red[prow*4+1] + Red[prow*4+2] + Red[prow*4+3]);
    float inv1 = 1.0f / (Red[(prow+8)*4] + Red[(prow+8)*4+1] + Red[(prow+8)*4+2] + Red[(prow+8)*4+3]);

    // y consumed as tf32 A of Wo GEMM -> round here
    #pragma unroll
    for (int nt = 0; nt < 3; nt++) {
        int col = wn*24 + nt*8 + 2*q;
        size_t b0 = ((size_t)((b*S_ + s0 + prow)*HQ_ + h))*DV_ + col;
        size_t b1 = ((size_t)((b*S_ + s0 + prow + 8)*HQ_ + h))*DV_ + col;
        *(float2*)(g_y + b0) = make_float2(f2tff(acc[nt][0]*inv0), f2tff(acc[nt][1]*inv0));
        *(float2*)(g_y + b1) = make_float2(f2tff(acc[nt][2]*inv1), f2tff(acc[nt][3]*inv1));
    }
}

// ---------------- launch ----------------
extern "C" void kernel_launch(void* const* d_in, const int* in_sizes, int n_in,
                              void* d_out, int out_size) {
    const float* x      = (const float*)d_in[0];
    const float* bn1_g  = (const float*)d_in[1];
    const float* bn1_ms = (const float*)d_in[2];
    const float* Wq     = (const float*)d_in[3];
    const float* Wk     = (const float*)d_in[4];
    const float* Wv     = (const float*)d_in[5];
    const float* qn_g   = (const float*)d_in[6];
    const float* qn_b   = (const float*)d_in[7];
    const float* kn_g   = (const float*)d_in[8];
    const float* kn_b   = (const float*)d_in[9];
    const float* vn_g   = (const float*)d_in[10];
    const float* vn_b   = (const float*)d_in[11];
    const float* Wo     = (const float*)d_in[12];
    const float* bo     = (const float*)d_in[13];
    const float* bn2_g  = (const float*)d_in[14];
    const float* bn2_ms = (const float*)d_in[15];
    float* out = (float*)d_out;

    float *ph, *pq, *pk, *pv, *py, *pwqkv, *pwo;
    cudaGetSymbolAddress((void**)&ph, g_h);
    cudaGetSymbolAddress((void**)&pq, g_q);
    cudaGetSymbolAddress((void**)&pk, g_k);
    cudaGetSymbolAddress((void**)&pv, g_v);
    cudaGetSymbolAddress((void**)&py, g_y);
    cudaGetSymbolAddress((void**)&pwqkv, g_wqkv);
    cudaGetSymbolAddress((void**)&pwo, g_wo);

    const int M = B_ * S_;
    const int gemm_smem = (2*AS_BUF + 2*BS_BUF) * 4;   // 73728 B

    cudaFuncSetAttribute(tf32gemm_kernel<1>, cudaFuncAttributeMaxDynamicSharedMemorySize, gemm_smem);
    cudaFuncSetAttribute(tf32gemm_kernel<2>, cudaFuncAttributeMaxDynamicSharedMemorySize, gemm_smem);
    cudaFuncSetAttribute(flash_kernel, cudaFuncAttributeMaxDynamicSharedMemorySize, FLASH_SMEM);

    // 0. weight transpose + tf32 conversion: dst[n][k]
    {
        dim3 blk(32, 8);
        transpose_tf32<<<dim3(2048/32, C_/32), blk>>>(Wq, pwqkv,               C_, 2048);
        transpose_tf32<<<dim3(512/32,  C_/32), blk>>>(Wk, pwqkv + 2048*C_,     C_, 512);
        transpose_tf32<<<dim3(384/32,  C_/32), blk>>>(Wv, pwqkv + 2560*C_,     C_, 384);
        transpose_tf32<<<dim3(C_/32,   C_/32), blk>>>(Wo, pwo,                 C_, C_);
    }

    // 1. rms_bn1
    rmsbn1_kernel<<<(B_*S_*C_/4 + 255)/256, 256>>>(x, bn1_g, bn1_ms);

    // 2. fused QKV projection
    tf32gemm_kernel<1><<<dim3(NQKV/128, M/128), 256, gemm_smem>>>(
        ph, pwqkv, nullptr, M, NQKV, C_, nullptr, nullptr, nullptr, pq, pk, pv);

    // 3. per-head LN (+RoPE)
    ln_head_kernel<DQK_, true,  HQ_ ><<<(B_*S_*HQ_)/8,  256>>>(pq, qn_g, qn_b);
    ln_head_kernel<DQK_, true,  HKV_><<<(B_*S_*HKV_)/8, 256>>>(pk, kn_g, kn_b);
    ln_head_kernel<DV_,  false, HKV_><<<(B_*S_*HKV_)/8, 256>>>(pv, vn_g, vn_b);

    // 4. attention
    flash_kernel<<<dim3(B_*HQ_, S_/64), 512, FLASH_SMEM>>>();

    // 5. output projection + bias + rms_bn2
    tf32gemm_kernel<2><<<dim3(C_/128, M/128), 256, gemm_smem>>>(
        py, pwo, out, M, C_, HQ_*DV_, bo, bn2_g, bn2_ms, nullptr, nullptr, nullptr);
}

// round 6
// speedup vs baseline: 3.0377x; 1.0784x over previous
#include <cuda_runtime.h>
#include <math.h>

#define B_ 2
#define S_ 2048
#define C_ 1536
#define HQ_ 16
#define HKV_ 4
#define DQK_ 128
#define DV_ 96
#define EPSF 1e-5f
#define NQKV 2944   // 2048 + 512 + 384

// ---------------- scratch ----------------
__device__ float g_h[B_*S_*C_];
__device__ float g_q[B_*S_*HQ_*DQK_];
__device__ float g_k[B_*S_*HKV_*DQK_];
__device__ float g_v[B_*S_*HKV_*DV_];
__device__ float g_y[B_*S_*HQ_*DV_];
__device__ float g_wqkv[NQKV*C_];      // tf32 Wq|Wk|Wv, TRANSPOSED [N][K]
__device__ float g_wo[C_*C_];          // tf32 Wo, TRANSPOSED [N][K]

// ---------------- helpers ----------------
__device__ __forceinline__ unsigned f2tf(float f) {
    unsigned u;
    asm("cvt.rna.tf32.f32 %0, %1;" : "=r"(u) : "f"(f));
    return u;
}
__device__ __forceinline__ float f2tff(float f) { return __uint_as_float(f2tf(f)); }
__device__ __forceinline__ void mma_tf32(float c[4], const unsigned a[4], const unsigned b[2]) {
    asm volatile(
        "mma.sync.aligned.m16n8k8.row.col.f32.tf32.tf32.f32 "
        "{%0,%1,%2,%3},{%4,%5,%6,%7},{%8,%9},{%0,%1,%2,%3};"
        : "+f"(c[0]), "+f"(c[1]), "+f"(c[2]), "+f"(c[3])
        : "r"(a[0]), "r"(a[1]), "r"(a[2]), "r"(a[3]), "r"(b[0]), "r"(b[1]));
}
#define LDSM4(d, addr) \
    asm volatile("ldmatrix.sync.aligned.m8n8.x4.shared.b16 {%0,%1,%2,%3}, [%4];" \
        : "=r"((d)[0]), "=r"((d)[1]), "=r"((d)[2]), "=r"((d)[3]) : "r"(addr))
__device__ __forceinline__ unsigned sm_u32(const void* p) {
    return (unsigned)__cvta_generic_to_shared(p);
}
__device__ __forceinline__ void cp16(void* smem, const void* gp) {
    unsigned s = sm_u32(smem);
    asm volatile("cp.async.cg.shared.global [%0], [%1], 16;\n" :: "r"(s), "l"(gp));
}
__device__ __forceinline__ void cp_commit() { asm volatile("cp.async.commit_group;\n"); }
__device__ __forceinline__ void cp_wait0() { asm volatile("cp.async.wait_group 0;\n"); }

// ---------------- 0. tiled transpose + tf32 round ----------------
__global__ void transpose_tf32(const float* __restrict__ src, float* __restrict__ dst,
                               int R, int Cc) {   // src [R][Cc], dst [Cc][R]
    __shared__ float tile[32][33];
    int x = blockIdx.x*32 + threadIdx.x;
    int y0 = blockIdx.y*32;
    #pragma unroll
    for (int j = threadIdx.y; j < 32; j += 8)
        tile[j][threadIdx.x] = src[(size_t)(y0+j)*Cc + x];
    __syncthreads();
    int xo = blockIdx.y*32 + threadIdx.x;
    int yo0 = blockIdx.x*32;
    #pragma unroll
    for (int j = threadIdx.y; j < 32; j += 8)
        dst[(size_t)(yo0+j)*R + xo] = f2tff(tile[threadIdx.x][j]);
}

// ---------------- 1. rms_bn1 (tf32-rounded output) ----------------
__global__ void rmsbn1_kernel(const float* __restrict__ x, const float* __restrict__ g,
                              const float* __restrict__ ms) {
    int idx = (blockIdx.x * blockDim.x + threadIdx.x) * 4;
    if (idx >= B_*S_*C_) return;
    float4 xv = *(const float4*)(x + idx);
    int c = idx % C_;
    float4 o;
    o.x = f2tff(xv.x * g[c+0] * rsqrtf(ms[c+0] + EPSF));
    o.y = f2tff(xv.y * g[c+1] * rsqrtf(ms[c+1] + EPSF));
    o.z = f2tff(xv.z * g[c+2] * rsqrtf(ms[c+2] + EPSF));
    o.w = f2tff(xv.w * g[c+3] * rsqrtf(ms[c+3] + EPSF));
    *(float4*)(g_h + idx) = o;
}

// ---------------- 2. tf32 GEMM 128x128x32, ldmatrix feeds, B transposed [N][K] ----
#define AS_STR 36
#define BS_STR 36
#define AS_BUF (128*AS_STR)
#define BS_BUF (128*BS_STR)

template<int MODE>
__global__ void __launch_bounds__(256, 2) tf32gemm_kernel(
    const float* __restrict__ A, const float* __restrict__ Bt, float* __restrict__ Cm,
    int M, int N, int K,
    const float* __restrict__ bias, const float* __restrict__ bng,
    const float* __restrict__ bnms,
    float* __restrict__ gq, float* __restrict__ gk, float* __restrict__ gv)
{
    extern __shared__ float sm[];
    float* As = sm;
    float* Bs = sm + 2*AS_BUF;

    int tid = threadIdx.x;
    int lane = tid & 31, wid = tid >> 5;
    int wm = wid & 3, wn = wid >> 2;
    int g = lane >> 2, q = lane & 3;
    int bx = blockIdx.x, by = blockIdx.y;

    int t7 = lane & 7, qb0 = (lane >> 3) & 1, qb1 = (lane >> 4) & 1;
    unsigned aoff[2], boff[4];
    #pragma unroll
    for (int mt = 0; mt < 2; mt++)
        aoff[mt] = ((wm*32 + mt*16 + qb0*8 + t7)*AS_STR + qb1*4)*4;
    #pragma unroll
    for (int nt2 = 0; nt2 < 4; nt2++)
        boff[nt2] = ((wn*64 + nt2*16 + qb1*8 + t7)*BS_STR + qb0*4)*4;

    float acc[2][8][4];
    #pragma unroll
    for (int mt = 0; mt < 2; mt++)
        #pragma unroll
        for (int nt = 0; nt < 8; nt++)
            #pragma unroll
            for (int i = 0; i < 4; i++) acc[mt][nt][i] = 0.f;

    const int nk = K / 32;
    {
        #pragma unroll
        for (int i = 0; i < 4; i++) {
            int f4 = tid + i*256;
            int r = f4 >> 3, c = (f4 & 7) * 4;
            cp16(As + r*AS_STR + c, A + (size_t)(by*128 + r)*K + c);
            cp16(Bs + r*BS_STR + c, Bt + (size_t)(bx*128 + r)*K + c);
        }
        cp_commit();
    }

    for (int kt = 0; kt < nk; kt++) {
        cp_wait0();
        __syncthreads();
        if (kt + 1 < nk) {
            float* Ad = As + ((kt+1)&1)*AS_BUF;
            float* Bd = Bs + ((kt+1)&1)*BS_BUF;
            int k0 = (kt+1)*32;
            #pragma unroll
            for (int i = 0; i < 4; i++) {
                int f4 = tid + i*256;
                int r = f4 >> 3, c = (f4 & 7) * 4;
                cp16(Ad + r*AS_STR + c, A + (size_t)(by*128 + r)*K + k0 + c);
                cp16(Bd + r*BS_STR + c, Bt + (size_t)(bx*128 + r)*K + k0 + c);
            }
            cp_commit();
        }
        unsigned uA = sm_u32(As + (kt&1)*AS_BUF);
        unsigned uB = sm_u32(Bs + (kt&1)*BS_BUF);
        #pragma unroll
        for (int kk = 0; kk < 32; kk += 8) {
            unsigned a[2][4], b[4][4];
            LDSM4(a[0], uA + aoff[0] + kk*4);
            LDSM4(a[1], uA + aoff[1] + kk*4);
            #pragma unroll
            for (int nt2 = 0; nt2 < 4; nt2++) LDSM4(b[nt2], uB + boff[nt2] + kk*4);
            #pragma unroll
            for (int mt = 0; mt < 2; mt++)
                #pragma unroll
                for (int nt = 0; nt < 8; nt++)
                    mma_tf32(acc[mt][nt], a[mt], &b[nt>>1][(nt&1)*2]);
        }
    }

    #pragma unroll
    for (int mt = 0; mt < 2; mt++) {
        int row = by*128 + wm*32 + mt*16 + g;
        #pragma unroll
        for (int nt = 0; nt < 8; nt++) {
            int col = bx*128 + wn*64 + nt*8 + 2*q;
            float v0 = acc[mt][nt][0], v1 = acc[mt][nt][1];
            float v2 = acc[mt][nt][2], v3 = acc[mt][nt][3];
            if (MODE == 2) {
                float s0 = bng[col]   * rsqrtf(bnms[col]   + EPSF);
                float s1 = bng[col+1] * rsqrtf(bnms[col+1] + EPSF);
                v0 = (v0 + bias[col])   * s0;
                v1 = (v1 + bias[col+1]) * s1;
                v2 = (v2 + bias[col])   * s0;
                v3 = (v3 + bias[col+1]) * s1;
                *(float2*)(Cm + (size_t)row*N + col)     = make_float2(v0, v1);
                *(float2*)(Cm + (size_t)(row+8)*N + col) = make_float2(v2, v3);
            } else {
                float *d0, *d1;
                if (col < 2048) {
                    d0 = gq + (size_t)row*2048 + col;
                    d1 = gq + (size_t)(row+8)*2048 + col;
                } else if (col < 2560) {
                    d0 = gk + (size_t)row*512 + (col - 2048);
                    d1 = gk + (size_t)(row+8)*512 + (col - 2048);
                } else {
                    d0 = gv + (size_t)row*384 + (col - 2560);
                    d1 = gv + (size_t)(row+8)*384 + (col - 2560);
                }
                *(float2*)d0 = make_float2(v0, v1);
                *(float2*)d1 = make_float2(v2, v3);
            }
        }
    }
}

// ---------------- 3. per-head LayerNorm (+RoPE), tf32-rounded output ----------
template<int D, bool ROPE, int H>
__global__ void ln_head_kernel(float* __restrict__ data, const float* __restrict__ gg,
                               const float* __restrict__ bb) {
    const int NV = D / 32;
    int gw = (blockIdx.x * blockDim.x + threadIdx.x) >> 5;
    int lane = threadIdx.x & 31;
    float* row = data + (size_t)gw * D;
    int s = (gw / H) % S_;
    int d0 = lane * NV;

    float vals[NV];
    #pragma unroll
    for (int i = 0; i < NV; i++) vals[i] = row[d0 + i];

    float sum = 0.f, sq = 0.f;
    #pragma unroll
    for (int i = 0; i < NV; i++) { sum += vals[i]; sq += vals[i]*vals[i]; }
    #pragma unroll
    for (int off = 16; off > 0; off >>= 1) {
        sum += __shfl_xor_sync(0xffffffffu, sum, off);
        sq  += __shfl_xor_sync(0xffffffffu, sq,  off);
    }
    float mean = sum * (1.0f / D);
    float var  = sq  * (1.0f / D) - mean * mean;
    float inv  = rsqrtf(var + EPSF);
    #pragma unroll
    for (int i = 0; i < NV; i++)
        vals[i] = (vals[i] - mean) * inv * gg[d0 + i] + bb[d0 + i];

    if (ROPE) {
        const double lg63 = log(1985.0) / 63.0;
        #pragma unroll
        for (int p = 0; p < NV/2; p++) {
            int fi = (d0 >> 1) + p;
            double geom = exp((double)fi * lg63);
            float invf = (float)(1.0 / ((double)fi + geom));
            float theta = (float)s * invf;
            float sn, cs;
            sincosf(theta, &sn, &cs);
            float x0 = vals[2*p], x1 = vals[2*p + 1];
            vals[2*p]     = x0 * cs - x1 * sn;
            vals[2*p + 1] = x1 * cs + x0 * sn;
        }
    }
    #pragma unroll
    for (int i = 0; i < NV; i++) row[d0 + i] = f2tff(vals[i]);
}

// ---------------- 4. GQA flash: 2 q-heads/CTA, 512 thr, 16 warps (8m x 2n) -------
// rows 0..127 = 2 heads x 64 queries; K/V tiles shared by both heads.
#define QS_STR 132
#define VS_STR 104
#define PS_STR 68
#define FQ_OFF 0
#define FK_OFF (128*QS_STR)             // 16896
#define FK_BUF (64*QS_STR)              // 8448
#define FV_OFF (FK_OFF + 2*FK_BUF)      // 33792
#define FV_BUF (64*VS_STR)              // 6656
#define FP_OFF (FV_OFF + 2*FV_BUF)      // 47104
#define FR_OFF (FP_OFF + 128*PS_STR)    // 55808
#define FLASH_SMEM ((FR_OFF + 256) * 4) // 224256 B

__global__ void __launch_bounds__(512) flash_kernel() {
    extern __shared__ float sm[];
    float* Qs = sm + FQ_OFF;
    float* Ks = sm + FK_OFF;
    float* Vs = sm + FV_OFF;
    float* Ps = sm + FP_OFF;
    float* Red = sm + FR_OFF;

    int bx = blockIdx.x;                   // [0,16): b*8 + kv*2 + hp
    int b  = bx >> 3;
    int kv = (bx >> 1) & 3;
    int hp = bx & 1;
    int s0 = blockIdx.y * 64;
    int tid = threadIdx.x;
    int lane = tid & 31, wid = tid >> 5;
    int wm = wid & 7, wn = wid >> 3;       // 8 x 2 warp grid: 16 rows x 32 keys each
    int g = lane >> 2, q = lane & 3;
    int t7 = lane & 7, qb0 = (lane >> 3) & 1, qb1 = (lane >> 4) & 1;

    unsigned qoff = ((wm*16 + qb0*8 + t7)*QS_STR + qb1*4)*4;
    unsigned koff0 = ((wn*32 +      qb1*8 + t7)*QS_STR + qb0*4)*4;
    unsigned koff1 = ((wn*32 + 16 + qb1*8 + t7)*QS_STR + qb0*4)*4;
    unsigned poff = ((wm*16 + qb0*8 + t7)*PS_STR + qb1*4)*4;
    unsigned uQ = sm_u32(Qs) + qoff;
    unsigned uP = sm_u32(Ps) + poff;

    float acc[6][4];
    #pragma unroll
    for (int nt = 0; nt < 6; nt++)
        #pragma unroll
        for (int i = 0; i < 4; i++) acc[nt][i] = 0.f;
    float rs[2] = {0.f, 0.f};

    const float scl = 0.08838834764831845f;   // 1/sqrt(128)

    // prefetch Q (128 rows: head e = r>>6, query r&63) + KV tile 0
    {
        #pragma unroll
        for (int i = 0; i < 8; i++) {
            int f4 = tid + i*512;
            int r = f4 >> 5, c = (f4 & 31) * 4;
            int he = kv + (hp*2 + (r >> 6))*HKV_;
            int qr = r & 63;
            cp16(Qs + r*QS_STR + c,
                 g_q + ((size_t)((b*S_ + s0 + qr)*HQ_ + he))*DQK_ + c);
        }
        const float* kb = g_k + ((size_t)(b*S_)*HKV_ + kv)*DQK_;
        const float* vb = g_v + ((size_t)(b*S_)*HKV_ + kv)*DV_;
        #pragma unroll
        for (int i = 0; i < 4; i++) {
            int f4 = tid + i*512;
            int r = f4 >> 5, c = (f4 & 31) * 4;
            cp16(Ks + r*QS_STR + c, kb + (size_t)r*HKV_*DQK_ + c);
        }
        #pragma unroll
        for (int i = 0; i < 3; i++) {
            int f4 = tid + i*512;
            int r = f4 / 24, c = (f4 % 24) * 4;
            cp16(Vs + r*VS_STR + c, vb + (size_t)r*HKV_*DV_ + c);
        }
        cp_commit();
    }

    int prow = wm*16 + g;

    for (int t0 = 0; t0 < 32; t0++) {
        cp_wait0();
        __syncthreads();
        if (t0 + 1 < 32) {
            const float* kb = g_k + ((size_t)(b*S_ + (t0+1)*64)*HKV_ + kv)*DQK_;
            const float* vb = g_v + ((size_t)(b*S_ + (t0+1)*64)*HKV_ + kv)*DV_;
            float* kd = Ks + ((t0+1)&1)*FK_BUF;
            float* vd = Vs + ((t0+1)&1)*FV_BUF;
            #pragma unroll
            for (int i = 0; i < 4; i++) {
                int f4 = tid + i*512;
                int r = f4 >> 5, c = (f4 & 31) * 4;
                cp16(kd + r*QS_STR + c, kb + (size_t)r*HKV_*DQK_ + c);
            }
            #pragma unroll
            for (int i = 0; i < 3; i++) {
                int f4 = tid + i*512;
                int r = f4 / 24, c = (f4 % 24) * 4;
                cp16(vd + r*VS_STR + c, vb + (size_t)r*HKV_*DV_ + c);
            }
            cp_commit();
        }
        unsigned uKbase = sm_u32(Ks + (t0&1)*FK_BUF);
        unsigned uK0 = uKbase + koff0, uK1 = uKbase + koff1;
        const float* Vb = Vs + (t0&1)*FV_BUF;

        // S = Q K^T (warp: 16 rows x 32 keys)
        float sacc[4][4];
        #pragma unroll
        for (int nt = 0; nt < 4; nt++)
            #pragma unroll
            for (int i = 0; i < 4; i++) sacc[nt][i] = 0.f;

        #pragma unroll
        for (int kk = 0; kk < DQK_; kk += 8) {
            unsigned aq[4], bk0[4], bk1[4];
            LDSM4(aq, uQ + kk*4);
            LDSM4(bk0, uK0 + kk*4);
            LDSM4(bk1, uK1 + kk*4);
            mma_tf32(sacc[0], aq, &bk0[0]);
            mma_tf32(sacc[1], aq, &bk0[2]);
            mma_tf32(sacc[2], aq, &bk1[0]);
            mma_tf32(sacc[3], aq, &bk1[2]);
        }

        // p = exp(5*tanh(l/5)) via u = e^{0.4 l}
        #pragma unroll
        for (int nt = 0; nt < 4; nt++) {
            #pragma unroll
            for (int ci = 0; ci < 4; ci++) {
                float l = sacc[nt][ci] * scl;
                float u = __expf(0.4f * l);
                float t = __fdividef(u - 1.0f, u + 1.0f);
                float p = __expf(5.0f * t);
                float pr = f2tff(p);
                rs[ci >> 1] += pr;
                int row = prow + ((ci >= 2) ? 8 : 0);
                int col = wn*32 + nt*8 + 2*q + (ci & 1);
                Ps[row*PS_STR + col] = pr;
            }
        }
        __syncthreads();

        // acc += P @ V (warp: 16 rows x 48 dv)
        #pragma unroll
        for (int kk = 0; kk < 64; kk += 8) {
            unsigned ap[4], bv[6][2];
            LDSM4(ap, uP + kk*4);
            #pragma unroll
            for (int nt = 0; nt < 6; nt++) {
                int dv = wn*48 + nt*8 + g;
                bv[nt][0] = __float_as_uint(Vb[(kk+q)*VS_STR + dv]);
                bv[nt][1] = __float_as_uint(Vb[(kk+q+4)*VS_STR + dv]);
            }
            #pragma unroll
            for (int nt = 0; nt < 6; nt++) mma_tf32(acc[nt], ap, bv[nt]);
        }
    }

    // row sums: reduce over q lanes, then across the 2 wn warps via smem
    #pragma unroll
    for (int i = 0; i < 2; i++) {
        rs[i] += __shfl_xor_sync(0xffffffffu, rs[i], 1);
        rs[i] += __shfl_xor_sync(0xffffffffu, rs[i], 2);
    }
    if (q == 0) {
        Red[prow*2 + wn]     = rs[0];
        Red[(prow+8)*2 + wn] = rs[1];
    }
    __syncthreads();
    float inv0 = 1.0f / (Red[prow*2] + Red[prow*2 + 1]);
    float inv1 = 1.0f / (Red[(prow+8)*2] + Red[(prow+8)*2 + 1]);

    // output: row -> head e = row/64, query = row%64; y consumed as tf32 by Wo GEMM
    #pragma unroll
    for (int nt = 0; nt < 6; nt++) {
        int col = wn*48 + nt*8 + 2*q;
        int r0 = prow, r1 = prow + 8;     // both within same head (wm*16+g+8 < next 64-blk)
        int he0 = kv + (hp*2 + (r0 >> 6))*HKV_;
        int he1 = kv + (hp*2 + (r1 >> 6))*HKV_;
        size_t b0 = ((size_t)((b*S_ + s0 + (r0 & 63))*HQ_ + he0))*DV_ + col;
        size_t b1 = ((size_t)((b*S_ + s0 + (r1 & 63))*HQ_ + he1))*DV_ + col;
        *(float2*)(g_y + b0) = make_float2(f2tff(acc[nt][0]*inv0), f2tff(acc[nt][1]*inv0));
        *(float2*)(g_y + b1) = make_float2(f2tff(acc[nt][2]*inv1), f2tff(acc[nt][3]*inv1));
    }
}

// ---------------- launch ----------------
extern "C" void kernel_launch(void* const* d_in, const int* in_sizes, int n_in,
                              void* d_out, int out_size) {
    const float* x      = (const float*)d_in[0];
    const float* bn1_g  = (const float*)d_in[1];
    const float* bn1_ms = (const float*)d_in[2];
    const float* Wq     = (const float*)d_in[3];
    const float* Wk     = (const float*)d_in[4];
    const float* Wv     = (const float*)d_in[5];
    const float* qn_g   = (const float*)d_in[6];
    const float* qn_b   = (const float*)d_in[7];
    const float* kn_g   = (const float*)d_in[8];
    const float* kn_b   = (const float*)d_in[9];
    const float* vn_g   = (const float*)d_in[10];
    const float* vn_b   = (const float*)d_in[11];
    const float* Wo     = (const float*)d_in[12];
    const float* bo     = (const float*)d_in[13];
    const float* bn2_g  = (const float*)d_in[14];
    const float* bn2_ms = (const float*)d_in[15];
    float* out = (float*)d_out;

    float *ph, *pq, *pk, *pv, *py, *pwqkv, *pwo;
    cudaGetSymbolAddress((void**)&ph, g_h);
    cudaGetSymbolAddress((void**)&pq, g_q);
    cudaGetSymbolAddress((void**)&pk, g_k);
    cudaGetSymbolAddress((void**)&pv, g_v);
    cudaGetSymbolAddress((void**)&py, g_y);
    cudaGetSymbolAddress((void**)&pwqkv, g_wqkv);
    cudaGetSymbolAddress((void**)&pwo, g_wo);

    const int M = B_ * S_;
    const int gemm_smem = (2*AS_BUF + 2*BS_BUF) * 4;

    cudaFuncSetAttribute(tf32gemm_kernel<1>, cudaFuncAttributeMaxDynamicSharedMemorySize, gemm_smem);
    cudaFuncSetAttribute(tf32gemm_kernel<2>, cudaFuncAttributeMaxDynamicSharedMemorySize, gemm_smem);
    cudaFuncSetAttribute(flash_kernel, cudaFuncAttributeMaxDynamicSharedMemorySize, FLASH_SMEM);

    // 0. weight transpose + tf32 conversion: dst[n][k]
    {
        dim3 blk(32, 8);
        transpose_tf32<<<dim3(2048/32, C_/32), blk>>>(Wq, pwqkv,           C_, 2048);
        transpose_tf32<<<dim3(512/32,  C_/32), blk>>>(Wk, pwqkv + 2048*C_, C_, 512);
        transpose_tf32<<<dim3(384/32,  C_/32), blk>>>(Wv, pwqkv + 2560*C_, C_, 384);
        transpose_tf32<<<dim3(C_/32,   C_/32), blk>>>(Wo, pwo,             C_, C_);
    }

    // 1. rms_bn1
    rmsbn1_kernel<<<(B_*S_*C_/4 + 255)/256, 256>>>(x, bn1_g, bn1_ms);

    // 2. fused QKV projection
    tf32gemm_kernel<1><<<dim3(NQKV/128, M/128), 256, gemm_smem>>>(
        ph, pwqkv, nullptr, M, NQKV, C_, nullptr, nullptr, nullptr, pq, pk, pv);

    // 3. per-head LN (+RoPE)
    ln_head_kernel<DQK_, true,  HQ_ ><<<(B_*S_*HQ_)/8,  256>>>(pq, qn_g, qn_b);
    ln_head_kernel<DQK_, true,  HKV_><<<(B_*S_*HKV_)/8, 256>>>(pk, kn_g, kn_b);
    ln_head_kernel<DV_,  false, HKV_><<<(B_*S_*HKV_)/8, 256>>>(pv, vn_g, vn_b);

    // 4. attention (GQA: 2 q-heads per CTA share K/V)
    flash_kernel<<<dim3(B_*HKV_*2, S_/64), 512, FLASH_SMEM>>>();

    // 5. output projection + bias + rms_bn2
    tf32gemm_kernel<2><<<dim3(C_/128, M/128), 256, gemm_smem>>>(
        py, pwo, out, M, C_, HQ_*DV_, bo, bn2_g, bn2_ms, nullptr, nullptr, nullptr);
}